// round 3
// baseline (speedup 1.0000x reference)
#include <cuda_runtime.h>
#include <cuda_bf16.h>
#include <cstdint>

#define MAX_N   131072
#define MAX_E   1700000
#define D       128
#define SCAN_B  512
#define MAX_BLK 512

// ---- scratch (__device__ globals; no allocations allowed) ----
__device__ __align__(16) float g_buf[(size_t)MAX_N * D];  // g = relu(LN(x)) @ W * dinv[row]
__device__ float g_dinv[MAX_N];
__device__ int   g_cnt[MAX_N];
__device__ int   g_rowptr[MAX_N + 1];
__device__ int   g_cur[MAX_N];
__device__ int   g_blk[MAX_BLK];
__device__ int   g_src[MAX_E];
__device__ int   g_e64;          // 1 if edge_index is int64, 0 if int32

// ---------------------------------------------------------------------------
// Edge-index dtype probe: int64 interpretation of int32-packed pairs yields
// values >= 2^32 with overwhelming probability.
__global__ void k_detect(const void* edges, long long nelem2E, int N) {
    if (threadIdx.x == 0 && blockIdx.x == 0) {
        const long long* p = (const long long*)edges;
        int ok = 1;
        const int K = 64;
        for (int i = 0; i < K; i++) {
            long long v = p[i];
            if (v < 0 || v >= (long long)N) { ok = 0; break; }
        }
        g_e64 = ok;
    }
}

__device__ __forceinline__ int load_idx(const void* edges, long long i, int e64) {
    if (e64) return (int)((const long long*)edges)[i];
    return ((const int*)edges)[i];
}

// ---------------------------------------------------------------------------
__global__ void k_zero_cnt(int n) {
    int i = blockIdx.x * blockDim.x + threadIdx.x;
    if (i < n) g_cnt[i] = 0;
}

// histogram over edge targets (second half of edges array)
__global__ void k_hist(const void* __restrict__ edges, int E, int N) {
    int e = blockIdx.x * blockDim.x + threadIdx.x;
    if (e < E) {
        int c = load_idx(edges, (long long)E + e, g_e64);
        if ((unsigned)c < (unsigned)N) atomicAdd(&g_cnt[c], 1);
    }
}

__global__ void k_dinv(int n) {
    int i = blockIdx.x * blockDim.x + threadIdx.x;
    if (i < n) g_dinv[i] = rsqrtf((float)(g_cnt[i] + 1));  // +1 self loop
}

// per-block exclusive scan of g_cnt -> g_rowptr (block-local), totals -> g_blk
__global__ void k_scan1(int n) {
    __shared__ int s[SCAN_B];
    const int tid = threadIdx.x;
    const int i   = blockIdx.x * SCAN_B + tid;
    const int v   = (i < n) ? g_cnt[i] : 0;
    s[tid] = v;
    __syncthreads();
    #pragma unroll
    for (int off = 1; off < SCAN_B; off <<= 1) {
        int t = (tid >= off) ? s[tid - off] : 0;
        __syncthreads();
        s[tid] += t;
        __syncthreads();
    }
    if (i < n) g_rowptr[i] = s[tid] - v;
    if (tid == SCAN_B - 1) g_blk[blockIdx.x] = s[tid];
}

__global__ void k_scan2(int nblk) {
    if (threadIdx.x == 0 && blockIdx.x == 0) {
        int run = 0;
        for (int b = 0; b < nblk; b++) { int t = g_blk[b]; g_blk[b] = run; run += t; }
    }
}

__global__ void k_scan3(int n, int E) {
    const int i = blockIdx.x * SCAN_B + threadIdx.x;
    if (i < n) {
        int r = g_rowptr[i] + g_blk[blockIdx.x];
        g_rowptr[i] = r;
        g_cur[i]    = r;
    }
    if (blockIdx.x == 0 && threadIdx.x == 0) g_rowptr[n] = E;
}

__global__ void k_fill(const void* __restrict__ edges, int E, int N) {
    int e = blockIdx.x * blockDim.x + threadIdx.x;
    if (e < E) {
        const int e64 = g_e64;
        int r = load_idx(edges, e, e64);
        int c = load_idx(edges, (long long)E + e, e64);
        if ((unsigned)c < (unsigned)N && (unsigned)r < (unsigned)N) {
            int pos = atomicAdd(&g_cur[c], 1);
            if (pos < MAX_E) g_src[pos] = r;
        }
    }
}

// ---------------------------------------------------------------------------
// Fused LayerNorm -> ReLU -> GEMM (x@W) -> * dinv[node], into g_buf.
__global__ void __launch_bounds__(256) fused_ln_gemm_kernel(
    const float* __restrict__ x,
    const float* __restrict__ gamma,
    const float* __restrict__ beta,
    const float* __restrict__ W, int N)
{
    __shared__ float a_s[128 * 65];
    const int tid  = threadIdx.x;
    const int warp = tid >> 5;
    const int lane = tid & 31;
    const int node0 = blockIdx.x * 64;

    #pragma unroll
    for (int rr = 0; rr < 8; rr++) {
        const int n = warp * 8 + rr;
        const int node = node0 + n;
        float v0 = 0.f, v1 = 0.f, v2 = 0.f, v3 = 0.f;
        if (node < N) {
            const float* xr = x + (size_t)node * D;
            v0 = xr[lane]; v1 = xr[lane + 32]; v2 = xr[lane + 64]; v3 = xr[lane + 96];
        }
        float s  = v0 + v1 + v2 + v3;
        float sq = v0 * v0 + v1 * v1 + v2 * v2 + v3 * v3;
        #pragma unroll
        for (int off = 16; off; off >>= 1) {
            s  += __shfl_xor_sync(0xFFFFFFFFu, s,  off);
            sq += __shfl_xor_sync(0xFFFFFFFFu, sq, off);
        }
        const float mu  = s * (1.0f / 128.0f);
        const float var = sq * (1.0f / 128.0f) - mu * mu;
        const float rs  = rsqrtf(var + 1e-5f);
        float t;
        t = fmaxf((v0 - mu) * rs * gamma[lane]      + beta[lane],      0.f); a_s[(lane)      * 65 + n] = t;
        t = fmaxf((v1 - mu) * rs * gamma[lane + 32] + beta[lane + 32], 0.f); a_s[(lane + 32) * 65 + n] = t;
        t = fmaxf((v2 - mu) * rs * gamma[lane + 64] + beta[lane + 64], 0.f); a_s[(lane + 64) * 65 + n] = t;
        t = fmaxf((v3 - mu) * rs * gamma[lane + 96] + beta[lane + 96], 0.f); a_s[(lane + 96) * 65 + n] = t;
    }
    __syncthreads();

    const int cg = lane;
    const int nb = warp * 8;
    float acc[8][4];
    #pragma unroll
    for (int j = 0; j < 8; j++)
        #pragma unroll
        for (int c = 0; c < 4; c++) acc[j][c] = 0.f;

    const float4* W4 = (const float4*)W;
    #pragma unroll 4
    for (int k = 0; k < 128; k++) {
        const float4 w = W4[k * 32 + cg];
        const float* ar = &a_s[k * 65 + nb];
        #pragma unroll
        for (int j = 0; j < 8; j++) {
            const float a = ar[j];
            acc[j][0] = fmaf(a, w.x, acc[j][0]);
            acc[j][1] = fmaf(a, w.y, acc[j][1]);
            acc[j][2] = fmaf(a, w.z, acc[j][2]);
            acc[j][3] = fmaf(a, w.w, acc[j][3]);
        }
    }

    #pragma unroll
    for (int j = 0; j < 8; j++) {
        const int node = node0 + nb + j;
        if (node < N) {
            const float dv = g_dinv[node];
            float4 r;
            r.x = acc[j][0] * dv; r.y = acc[j][1] * dv;
            r.z = acc[j][2] * dv; r.w = acc[j][3] * dv;
            ((float4*)(g_buf + (size_t)node * D))[cg] = r;
        }
    }
}

// ---------------------------------------------------------------------------
// Warp-per-node gather: out[i] = dinv[i]*(g[i] + sum_j g[src_j]) + bias
__global__ void __launch_bounds__(256) k_aggr(float* __restrict__ out,
                                              const float* __restrict__ bias, int N)
{
    const int gt   = blockIdx.x * blockDim.x + threadIdx.x;
    const int node = gt >> 5;
    const int lane = gt & 31;
    if (node >= N) return;

    const int start = g_rowptr[node];
    const int end   = g_rowptr[node + 1];

    float4 acc = ((const float4*)(g_buf + (size_t)node * D))[lane];  // self loop

    int k = start;
    for (; k + 4 <= end; k += 4) {
        const int j0 = g_src[k], j1 = g_src[k + 1], j2 = g_src[k + 2], j3 = g_src[k + 3];
        const float4 v0 = ((const float4*)(g_buf + (size_t)j0 * D))[lane];
        const float4 v1 = ((const float4*)(g_buf + (size_t)j1 * D))[lane];
        const float4 v2 = ((const float4*)(g_buf + (size_t)j2 * D))[lane];
        const float4 v3 = ((const float4*)(g_buf + (size_t)j3 * D))[lane];
        acc.x += v0.x + v1.x + v2.x + v3.x;
        acc.y += v0.y + v1.y + v2.y + v3.y;
        acc.z += v0.z + v1.z + v2.z + v3.z;
        acc.w += v0.w + v1.w + v2.w + v3.w;
    }
    for (; k < end; k++) {
        const float4 v = ((const float4*)(g_buf + (size_t)g_src[k] * D))[lane];
        acc.x += v.x; acc.y += v.y; acc.z += v.z; acc.w += v.w;
    }

    const float  dv = g_dinv[node];
    const float4 b  = ((const float4*)bias)[lane];
    float4 r;
    r.x = acc.x * dv + b.x;
    r.y = acc.y * dv + b.y;
    r.z = acc.z * dv + b.z;
    r.w = acc.w * dv + b.w;
    ((float4*)(out + (size_t)node * D))[lane] = r;
}

// ---------------------------------------------------------------------------
extern "C" void kernel_launch(void* const* d_in, const int* in_sizes, int n_in,
                              void* d_out, int out_size)
{
    const float* x     = (const float*)d_in[0];
    const void*  edges = (const void*)d_in[1];
    const float* gamma = (const float*)d_in[2];
    const float* beta  = (const float*)d_in[3];
    const float* W     = (const float*)d_in[4];
    const float* bias  = (const float*)d_in[5];
    float*       out   = (float*)d_out;

    const int N = in_sizes[0] / D;
    const int E = in_sizes[1] / 2;

    const int nblk = (N + SCAN_B - 1) / SCAN_B;

    k_detect<<<1, 32>>>(edges, (long long)in_sizes[1], N);
    k_zero_cnt<<<(N + 255) / 256, 256>>>(N);
    k_hist<<<(E + 255) / 256, 256>>>(edges, E, N);
    k_dinv<<<(N + 255) / 256, 256>>>(N);
    k_scan1<<<nblk, SCAN_B>>>(N);
    k_scan2<<<1, 32>>>(nblk);
    k_scan3<<<nblk, SCAN_B>>>(N, E);
    k_fill<<<(E + 255) / 256, 256>>>(edges, E, N);

    fused_ln_gemm_kernel<<<(N + 63) / 64, 256>>>(x, gamma, beta, W, N);

    k_aggr<<<(N * 32 + 255) / 256, 256>>>(out, bias, N);
}

// round 5
// speedup vs baseline: 1.1266x; 1.1266x over previous
#include <cuda_runtime.h>
#include <cuda_fp16.h>
#include <cstdint>

#define MAX_N   131072
#define MAX_E   1700000
#define D       128
#define SCAN_B  512
#define MAX_BLK 512

// ---- scratch (__device__ globals; no allocations allowed) ----
__device__ __align__(16) __half2 g_bufh[(size_t)MAX_N * 64];  // h = relu(LN(x))@W, fp16
__device__ float g_dinv[MAX_N];
__device__ int   g_cnt[MAX_N];
__device__ int   g_rowptr[MAX_N + 1];
__device__ int   g_cur[MAX_N];
__device__ int   g_blk[MAX_BLK];
__device__ int   g_src[MAX_E];
__device__ int   g_e64;          // 1 if edge_index is int64, 0 if int32

// ---------------------------------------------------------------------------
__device__ __forceinline__ unsigned long long fma2(unsigned long long a,
                                                   unsigned long long b,
                                                   unsigned long long c) {
    unsigned long long d;
    asm("fma.rn.f32x2 %0, %1, %2, %3;" : "=l"(d) : "l"(a), "l"(b), "l"(c));
    return d;
}
__device__ __forceinline__ unsigned long long pk2(float x) {  // (x, x) packed
    unsigned long long d;
    asm("mov.b64 %0, {%1, %1};" : "=l"(d) : "f"(x));
    return d;
}
__device__ __forceinline__ float lo32(unsigned long long u) {
    return __uint_as_float((unsigned)(u & 0xFFFFFFFFull));
}
__device__ __forceinline__ float hi32(unsigned long long u) {
    return __uint_as_float((unsigned)(u >> 32));
}
// bit-reinterpret helpers (no standard intrinsic exists for these)
__device__ __forceinline__ unsigned h2_as_u32(__half2 h) {
    union { __half2 h; unsigned u; } cvt; cvt.h = h; return cvt.u;
}
__device__ __forceinline__ __half2 u32_as_h2(unsigned u) {
    union { unsigned u; __half2 h; } cvt; cvt.u = u; return cvt.h;
}

// ---------------------------------------------------------------------------
// Edge-index dtype probe: int64 view of int32-packed pairs gives huge values.
__global__ void k_detect(const void* edges, int N) {
    if (threadIdx.x == 0 && blockIdx.x == 0) {
        const long long* p = (const long long*)edges;
        int ok = 1;
        for (int i = 0; i < 64; i++) {
            long long v = p[i];
            if (v < 0 || v >= (long long)N) { ok = 0; break; }
        }
        g_e64 = ok;
    }
}

__device__ __forceinline__ int load_idx(const void* edges, long long i, int e64) {
    if (e64) return (int)((const long long*)edges)[i];
    return ((const int*)edges)[i];
}

__global__ void k_zero_cnt(int n) {
    int i = blockIdx.x * blockDim.x + threadIdx.x;
    if (i < n) g_cnt[i] = 0;
}

__global__ void k_hist(const void* __restrict__ edges, int E, int N) {
    int e = blockIdx.x * blockDim.x + threadIdx.x;
    if (e < E) {
        int c = load_idx(edges, (long long)E + e, g_e64);
        if ((unsigned)c < (unsigned)N) atomicAdd(&g_cnt[c], 1);
    }
}

__global__ void k_dinv(int n) {
    int i = blockIdx.x * blockDim.x + threadIdx.x;
    if (i < n) g_dinv[i] = rsqrtf((float)(g_cnt[i] + 1));  // +1 self loop
}

__global__ void k_scan1(int n) {
    __shared__ int s[SCAN_B];
    const int tid = threadIdx.x;
    const int i   = blockIdx.x * SCAN_B + tid;
    const int v   = (i < n) ? g_cnt[i] : 0;
    s[tid] = v;
    __syncthreads();
    #pragma unroll
    for (int off = 1; off < SCAN_B; off <<= 1) {
        int t = (tid >= off) ? s[tid - off] : 0;
        __syncthreads();
        s[tid] += t;
        __syncthreads();
    }
    if (i < n) g_rowptr[i] = s[tid] - v;
    if (tid == SCAN_B - 1) g_blk[blockIdx.x] = s[tid];
}

__global__ void k_scan2(int nblk) {
    if (threadIdx.x == 0 && blockIdx.x == 0) {
        int run = 0;
        for (int b = 0; b < nblk; b++) { int t = g_blk[b]; g_blk[b] = run; run += t; }
    }
}

__global__ void k_scan3(int n, int E) {
    const int i = blockIdx.x * SCAN_B + threadIdx.x;
    if (i < n) {
        int r = g_rowptr[i] + g_blk[blockIdx.x];
        g_rowptr[i] = r;
        g_cur[i]    = r;
    }
    if (blockIdx.x == 0 && threadIdx.x == 0) g_rowptr[n] = E;
}

__global__ void k_fill(const void* __restrict__ edges, int E, int N) {
    int e = blockIdx.x * blockDim.x + threadIdx.x;
    if (e < E) {
        const int e64 = g_e64;
        int r = load_idx(edges, e, e64);
        int c = load_idx(edges, (long long)E + e, e64);
        if ((unsigned)c < (unsigned)N && (unsigned)r < (unsigned)N) {
            int pos = atomicAdd(&g_cur[c], 1);
            if (pos < MAX_E) g_src[pos] = r;
        }
    }
}

// ---------------------------------------------------------------------------
// Fused LayerNorm -> ReLU -> GEMM (x@W), fp16 output into g_bufh.
// 256 threads / block, 64 nodes / block. Packed fma.rn.f32x2 over node pairs.
__global__ void __launch_bounds__(256) fused_ln_gemm_kernel(
    const float* __restrict__ x,
    const float* __restrict__ gamma,
    const float* __restrict__ beta,
    const float* __restrict__ W, int N)
{
    __shared__ float a_s[128 * 72];   // k-major: a_s[k*72 + n], n in [0,64)
    const int tid  = threadIdx.x;
    const int warp = tid >> 5;
    const int lane = tid & 31;
    const int node0 = blockIdx.x * 64;

    // ---- Phase A: LayerNorm + ReLU into shared (k-major) ----
    #pragma unroll
    for (int rr = 0; rr < 8; rr++) {
        const int n = warp * 8 + rr;
        const int node = node0 + n;
        float v0 = 0.f, v1 = 0.f, v2 = 0.f, v3 = 0.f;
        if (node < N) {
            const float* xr = x + (size_t)node * D;
            v0 = xr[lane]; v1 = xr[lane + 32]; v2 = xr[lane + 64]; v3 = xr[lane + 96];
        }
        float s  = v0 + v1 + v2 + v3;
        float sq = v0 * v0 + v1 * v1 + v2 * v2 + v3 * v3;
        #pragma unroll
        for (int off = 16; off; off >>= 1) {
            s  += __shfl_xor_sync(0xFFFFFFFFu, s,  off);
            sq += __shfl_xor_sync(0xFFFFFFFFu, sq, off);
        }
        const float mu  = s * (1.0f / 128.0f);
        const float var = sq * (1.0f / 128.0f) - mu * mu;
        const float rs  = rsqrtf(var + 1e-5f);
        float t;
        t = fmaxf((v0 - mu) * rs * gamma[lane]      + beta[lane],      0.f); a_s[(lane)      * 72 + n] = t;
        t = fmaxf((v1 - mu) * rs * gamma[lane + 32] + beta[lane + 32], 0.f); a_s[(lane + 32) * 72 + n] = t;
        t = fmaxf((v2 - mu) * rs * gamma[lane + 64] + beta[lane + 64], 0.f); a_s[(lane + 64) * 72 + n] = t;
        t = fmaxf((v3 - mu) * rs * gamma[lane + 96] + beta[lane + 96], 0.f); a_s[(lane + 96) * 72 + n] = t;
    }
    __syncthreads();

    // ---- Phase B: packed GEMM. lane -> cols [4cg, 4cg+4), warp -> nodes [8w, 8w+8)
    const int cg = lane;
    const int nb = warp * 8;
    // acc[p][c]: packed pair (node nb+2p lo, node nb+2p+1 hi), col 4cg+c
    unsigned long long acc[4][4];
    #pragma unroll
    for (int p = 0; p < 4; p++)
        #pragma unroll
        for (int c = 0; c < 4; c++) acc[p][c] = 0ull;

    const float4* W4 = (const float4*)W;   // W row-major [k][c]
    #pragma unroll 8
    for (int k = 0; k < 128; k++) {
        const float4 w = W4[k * 32 + cg];
        unsigned long long wp[4] = { pk2(w.x), pk2(w.y), pk2(w.z), pk2(w.w) };
        const double2* ad = (const double2*)&a_s[k * 72 + nb];
        const double2 a01 = ad[0];          // (a[0],a[1]), (a[2],a[3])
        const double2 a23 = ad[1];          // (a[4],a[5]), (a[6],a[7])
        unsigned long long ap[4] = {
            (unsigned long long)__double_as_longlong(a01.x),
            (unsigned long long)__double_as_longlong(a01.y),
            (unsigned long long)__double_as_longlong(a23.x),
            (unsigned long long)__double_as_longlong(a23.y)
        };
        #pragma unroll
        for (int p = 0; p < 4; p++)
            #pragma unroll
            for (int c = 0; c < 4; c++)
                acc[p][c] = fma2(ap[p], wp[c], acc[p][c]);
    }

    // ---- Epilogue: fp16 store ----
    #pragma unroll
    for (int p = 0; p < 4; p++) {
        const int nA = node0 + nb + 2 * p;
        const int nB = nA + 1;
        if (nA < N) {
            __half2 h01 = __floats2half2_rn(lo32(acc[p][0]), lo32(acc[p][1]));
            __half2 h23 = __floats2half2_rn(lo32(acc[p][2]), lo32(acc[p][3]));
            uint2 u; u.x = h2_as_u32(h01); u.y = h2_as_u32(h23);
            ((uint2*)(g_bufh + (size_t)nA * 64))[cg] = u;
        }
        if (nB < N) {
            __half2 h01 = __floats2half2_rn(hi32(acc[p][0]), hi32(acc[p][1]));
            __half2 h23 = __floats2half2_rn(hi32(acc[p][2]), hi32(acc[p][3]));
            uint2 u; u.x = h2_as_u32(h01); u.y = h2_as_u32(h23);
            ((uint2*)(g_bufh + (size_t)nB * 64))[cg] = u;
        }
    }
}

// ---------------------------------------------------------------------------
// Warp-per-node gather: out[i] = dinv[i]*(sum_j dinv[j]*h[j] + dinv[i]*h[i]) + bias
__global__ void __launch_bounds__(256) k_aggr(float* __restrict__ out,
                                              const float* __restrict__ bias, int N)
{
    const int gt   = blockIdx.x * blockDim.x + threadIdx.x;
    const int node = gt >> 5;
    const int lane = gt & 31;
    if (node >= N) return;

    const int start = g_rowptr[node];
    const int end   = g_rowptr[node + 1];
    const float dvi = g_dinv[node];

    float a0 = 0.f, a1 = 0.f, a2 = 0.f, a3 = 0.f;
    // self loop
    {
        const uint2 u = ((const uint2*)(g_bufh + (size_t)node * 64))[lane];
        const float2 f0 = __half22float2(u32_as_h2(u.x));
        const float2 f1 = __half22float2(u32_as_h2(u.y));
        a0 = fmaf(dvi, f0.x, a0); a1 = fmaf(dvi, f0.y, a1);
        a2 = fmaf(dvi, f1.x, a2); a3 = fmaf(dvi, f1.y, a3);
    }

    int k = start;
    for (; k + 4 <= end; k += 4) {
        const int j0 = g_src[k], j1 = g_src[k + 1], j2 = g_src[k + 2], j3 = g_src[k + 3];
        const float d0 = g_dinv[j0], d1 = g_dinv[j1], d2 = g_dinv[j2], d3 = g_dinv[j3];
        const uint2 u0 = ((const uint2*)(g_bufh + (size_t)j0 * 64))[lane];
        const uint2 u1 = ((const uint2*)(g_bufh + (size_t)j1 * 64))[lane];
        const uint2 u2 = ((const uint2*)(g_bufh + (size_t)j2 * 64))[lane];
        const uint2 u3 = ((const uint2*)(g_bufh + (size_t)j3 * 64))[lane];
        float2 f;
        f = __half22float2(u32_as_h2(u0.x)); a0 = fmaf(d0, f.x, a0); a1 = fmaf(d0, f.y, a1);
        f = __half22float2(u32_as_h2(u0.y)); a2 = fmaf(d0, f.x, a2); a3 = fmaf(d0, f.y, a3);
        f = __half22float2(u32_as_h2(u1.x)); a0 = fmaf(d1, f.x, a0); a1 = fmaf(d1, f.y, a1);
        f = __half22float2(u32_as_h2(u1.y)); a2 = fmaf(d1, f.x, a2); a3 = fmaf(d1, f.y, a3);
        f = __half22float2(u32_as_h2(u2.x)); a0 = fmaf(d2, f.x, a0); a1 = fmaf(d2, f.y, a1);
        f = __half22float2(u32_as_h2(u2.y)); a2 = fmaf(d2, f.x, a2); a3 = fmaf(d2, f.y, a3);
        f = __half22float2(u32_as_h2(u3.x)); a0 = fmaf(d3, f.x, a0); a1 = fmaf(d3, f.y, a1);
        f = __half22float2(u32_as_h2(u3.y)); a2 = fmaf(d3, f.x, a2); a3 = fmaf(d3, f.y, a3);
    }
    for (; k < end; k++) {
        const int j = g_src[k];
        const float dj = g_dinv[j];
        const uint2 u = ((const uint2*)(g_bufh + (size_t)j * 64))[lane];
        float2 f;
        f = __half22float2(u32_as_h2(u.x)); a0 = fmaf(dj, f.x, a0); a1 = fmaf(dj, f.y, a1);
        f = __half22float2(u32_as_h2(u.y)); a2 = fmaf(dj, f.x, a2); a3 = fmaf(dj, f.y, a3);
    }

    const float4 b = ((const float4*)bias)[lane];
    float4 r;
    r.x = a0 * dvi + b.x;
    r.y = a1 * dvi + b.y;
    r.z = a2 * dvi + b.z;
    r.w = a3 * dvi + b.w;
    ((float4*)(out + (size_t)node * D))[lane] = r;
}

// ---------------------------------------------------------------------------
extern "C" void kernel_launch(void* const* d_in, const int* in_sizes, int n_in,
                              void* d_out, int out_size)
{
    const float* x     = (const float*)d_in[0];
    const void*  edges = (const void*)d_in[1];
    const float* gamma = (const float*)d_in[2];
    const float* beta  = (const float*)d_in[3];
    const float* W     = (const float*)d_in[4];
    const float* bias  = (const float*)d_in[5];
    float*       out   = (float*)d_out;

    const int N = in_sizes[0] / D;
    const int E = in_sizes[1] / 2;
    const int nblk = (N + SCAN_B - 1) / SCAN_B;

    k_detect<<<1, 32>>>(edges, N);
    k_zero_cnt<<<(N + 255) / 256, 256>>>(N);
    k_hist<<<(E + 255) / 256, 256>>>(edges, E, N);
    k_dinv<<<(N + 255) / 256, 256>>>(N);
    k_scan1<<<nblk, SCAN_B>>>(N);
    k_scan2<<<1, 32>>>(nblk);
    k_scan3<<<nblk, SCAN_B>>>(N, E);
    k_fill<<<(E + 255) / 256, 256>>>(edges, E, N);

    fused_ln_gemm_kernel<<<(N + 63) / 64, 256>>>(x, gamma, beta, W, N);

    k_aggr<<<(N * 32 + 255) / 256, 256>>>(out, bias, N);
}

// round 6
// speedup vs baseline: 1.1550x; 1.0252x over previous
#include <cuda_runtime.h>
#include <cuda_fp16.h>
#include <cstdint>

#define MAX_N   131072
#define MAX_E   1700000
#define D       128
#define SCAN_B  512
#define MAX_BLK 256   // MAX_N / SCAN_B

// ---- scratch (__device__ globals; no allocations allowed) ----
__device__ __align__(16) __half2 g_bufh[(size_t)MAX_N * 64];  // h = relu(LN(x))@W, fp16
__device__ float g_dinv[MAX_N];
__device__ int   g_cnt[MAX_N];
__device__ int   g_rowptr[MAX_N + 1];
__device__ int   g_cur[MAX_N];
__device__ int   g_blk[MAX_BLK];
__device__ int   g_src[MAX_E];
__device__ int   g_e64;          // 1 if edge_index is int64, 0 if int32

// ---------------------------------------------------------------------------
__device__ __forceinline__ unsigned long long fma2(unsigned long long a,
                                                   unsigned long long b,
                                                   unsigned long long c) {
    unsigned long long d;
    asm("fma.rn.f32x2 %0, %1, %2, %3;" : "=l"(d) : "l"(a), "l"(b), "l"(c));
    return d;
}
__device__ __forceinline__ unsigned long long pk2(float x) {  // (x, x) packed
    unsigned long long d;
    asm("mov.b64 %0, {%1, %1};" : "=l"(d) : "f"(x));
    return d;
}
__device__ __forceinline__ float lo32(unsigned long long u) {
    return __uint_as_float((unsigned)(u & 0xFFFFFFFFull));
}
__device__ __forceinline__ float hi32(unsigned long long u) {
    return __uint_as_float((unsigned)(u >> 32));
}
__device__ __forceinline__ unsigned h2_as_u32(__half2 h) {
    union { __half2 h; unsigned u; } cvt; cvt.h = h; return cvt.u;
}
__device__ __forceinline__ __half2 u32_as_h2(unsigned u) {
    union { unsigned u; __half2 h; } cvt; cvt.u = u; return cvt.h;
}

__device__ __forceinline__ int load_idx(const void* edges, long long i, int e64) {
    if (e64) return (int)((const long long*)edges)[i];
    return ((const int*)edges)[i];
}

// ---------------------------------------------------------------------------
// K1: zero g_cnt + parallel edge-dtype probe (block 0, 64 threads, 1 load each).
__global__ void k_init(const void* __restrict__ edges, int N, int n) {
    __shared__ int bad;
    const int i = blockIdx.x * blockDim.x + threadIdx.x;
    if (i < n) g_cnt[i] = 0;
    if (blockIdx.x == 0) {
        if (threadIdx.x == 0) bad = 0;
        __syncthreads();
        if (threadIdx.x < 64) {
            long long v = ((const long long*)edges)[threadIdx.x];
            if (v < 0 || v >= (long long)N) atomicOr(&bad, 1);
        }
        __syncthreads();
        if (threadIdx.x == 0) g_e64 = bad ? 0 : 1;
    }
}

// K2: histogram over edge targets (second half of edges array)
__global__ void k_hist(const void* __restrict__ edges, int E, int N) {
    int e = blockIdx.x * blockDim.x + threadIdx.x;
    if (e < E) {
        int c = load_idx(edges, (long long)E + e, g_e64);
        if ((unsigned)c < (unsigned)N) atomicAdd(&g_cnt[c], 1);
    }
}

// K3: per-block exclusive scan of g_cnt -> g_rowptr (block-local), totals -> g_blk,
//     fused dinv = rsqrt(cnt+1).
__global__ void k_scan1(int n) {
    __shared__ int s[SCAN_B];
    const int tid = threadIdx.x;
    const int i   = blockIdx.x * SCAN_B + tid;
    const int v   = (i < n) ? g_cnt[i] : 0;
    if (i < n) g_dinv[i] = rsqrtf((float)(v + 1));   // +1 self loop
    s[tid] = v;
    __syncthreads();
    #pragma unroll
    for (int off = 1; off < SCAN_B; off <<= 1) {
        int t = (tid >= off) ? s[tid - off] : 0;
        __syncthreads();
        s[tid] += t;
        __syncthreads();
    }
    if (i < n) g_rowptr[i] = s[tid] - v;
    if (tid == SCAN_B - 1) g_blk[blockIdx.x] = s[tid];
}

// K4: parallel exclusive scan of block totals (single block, nblk <= 256)
__global__ void k_scan2(int nblk) {
    __shared__ int s[MAX_BLK];
    const int tid = threadIdx.x;
    const int v = (tid < nblk) ? g_blk[tid] : 0;
    s[tid] = v;
    __syncthreads();
    #pragma unroll
    for (int off = 1; off < MAX_BLK; off <<= 1) {
        int t = (tid >= off) ? s[tid - off] : 0;
        __syncthreads();
        s[tid] += t;
        __syncthreads();
    }
    if (tid < nblk) g_blk[tid] = s[tid] - v;   // exclusive
}

// K5: add block offsets; init cursors; set rowptr[N]
__global__ void k_scan3(int n, int E) {
    const int i = blockIdx.x * SCAN_B + threadIdx.x;
    if (i < n) {
        int r = g_rowptr[i] + g_blk[blockIdx.x];
        g_rowptr[i] = r;
        g_cur[i]    = r;
    }
    if (blockIdx.x == 0 && threadIdx.x == 0) g_rowptr[n] = E;
}

// K6: CSR fill
__global__ void k_fill(const void* __restrict__ edges, int E, int N) {
    int e = blockIdx.x * blockDim.x + threadIdx.x;
    if (e < E) {
        const int e64 = g_e64;
        int r = load_idx(edges, e, e64);
        int c = load_idx(edges, (long long)E + e, e64);
        if ((unsigned)c < (unsigned)N && (unsigned)r < (unsigned)N) {
            int pos = atomicAdd(&g_cur[c], 1);
            if (pos < MAX_E) g_src[pos] = r;
        }
    }
}

// ---------------------------------------------------------------------------
// K7: Fused LayerNorm -> ReLU -> GEMM (x@W), fp16 output into g_bufh.
// 256 threads / block, 64 nodes / block. Packed fma.rn.f32x2 over node pairs.
__global__ void __launch_bounds__(256) fused_ln_gemm_kernel(
    const float* __restrict__ x,
    const float* __restrict__ gamma,
    const float* __restrict__ beta,
    const float* __restrict__ W, int N)
{
    __shared__ float a_s[128 * 72];   // k-major: a_s[k*72 + n], n in [0,64)
    const int tid  = threadIdx.x;
    const int warp = tid >> 5;
    const int lane = tid & 31;
    const int node0 = blockIdx.x * 64;

    // ---- Phase A: LayerNorm + ReLU into shared (k-major) ----
    #pragma unroll
    for (int rr = 0; rr < 8; rr++) {
        const int n = warp * 8 + rr;
        const int node = node0 + n;
        float v0 = 0.f, v1 = 0.f, v2 = 0.f, v3 = 0.f;
        if (node < N) {
            const float* xr = x + (size_t)node * D;
            v0 = xr[lane]; v1 = xr[lane + 32]; v2 = xr[lane + 64]; v3 = xr[lane + 96];
        }
        float s  = v0 + v1 + v2 + v3;
        float sq = v0 * v0 + v1 * v1 + v2 * v2 + v3 * v3;
        #pragma unroll
        for (int off = 16; off; off >>= 1) {
            s  += __shfl_xor_sync(0xFFFFFFFFu, s,  off);
            sq += __shfl_xor_sync(0xFFFFFFFFu, sq, off);
        }
        const float mu  = s * (1.0f / 128.0f);
        const float var = sq * (1.0f / 128.0f) - mu * mu;
        const float rs  = rsqrtf(var + 1e-5f);
        float t;
        t = fmaxf((v0 - mu) * rs * gamma[lane]      + beta[lane],      0.f); a_s[(lane)      * 72 + n] = t;
        t = fmaxf((v1 - mu) * rs * gamma[lane + 32] + beta[lane + 32], 0.f); a_s[(lane + 32) * 72 + n] = t;
        t = fmaxf((v2 - mu) * rs * gamma[lane + 64] + beta[lane + 64], 0.f); a_s[(lane + 64) * 72 + n] = t;
        t = fmaxf((v3 - mu) * rs * gamma[lane + 96] + beta[lane + 96], 0.f); a_s[(lane + 96) * 72 + n] = t;
    }
    __syncthreads();

    // ---- Phase B: packed GEMM ----
    const int cg = lane;
    const int nb = warp * 8;
    unsigned long long acc[4][4];
    #pragma unroll
    for (int p = 0; p < 4; p++)
        #pragma unroll
        for (int c = 0; c < 4; c++) acc[p][c] = 0ull;

    const float4* W4 = (const float4*)W;
    #pragma unroll 8
    for (int k = 0; k < 128; k++) {
        const float4 w = W4[k * 32 + cg];
        unsigned long long wp[4] = { pk2(w.x), pk2(w.y), pk2(w.z), pk2(w.w) };
        const double2* ad = (const double2*)&a_s[k * 72 + nb];
        const double2 a01 = ad[0];
        const double2 a23 = ad[1];
        unsigned long long ap[4] = {
            (unsigned long long)__double_as_longlong(a01.x),
            (unsigned long long)__double_as_longlong(a01.y),
            (unsigned long long)__double_as_longlong(a23.x),
            (unsigned long long)__double_as_longlong(a23.y)
        };
        #pragma unroll
        for (int p = 0; p < 4; p++)
            #pragma unroll
            for (int c = 0; c < 4; c++)
                acc[p][c] = fma2(ap[p], wp[c], acc[p][c]);
    }

    // ---- Epilogue: fp16 store ----
    #pragma unroll
    for (int p = 0; p < 4; p++) {
        const int nA = node0 + nb + 2 * p;
        const int nB = nA + 1;
        if (nA < N) {
            __half2 h01 = __floats2half2_rn(lo32(acc[p][0]), lo32(acc[p][1]));
            __half2 h23 = __floats2half2_rn(lo32(acc[p][2]), lo32(acc[p][3]));
            uint2 u; u.x = h2_as_u32(h01); u.y = h2_as_u32(h23);
            ((uint2*)(g_bufh + (size_t)nA * 64))[cg] = u;
        }
        if (nB < N) {
            __half2 h01 = __floats2half2_rn(hi32(acc[p][0]), hi32(acc[p][1]));
            __half2 h23 = __floats2half2_rn(hi32(acc[p][2]), hi32(acc[p][3]));
            uint2 u; u.x = h2_as_u32(h01); u.y = h2_as_u32(h23);
            ((uint2*)(g_bufh + (size_t)nB * 64))[cg] = u;
        }
    }
}

// ---------------------------------------------------------------------------
// K8: warp-per-node gather: out[i] = dinv[i]*(sum_j dinv[j]*h[j] + dinv[i]*h[i]) + bias
__global__ void __launch_bounds__(256) k_aggr(float* __restrict__ out,
                                              const float* __restrict__ bias, int N)
{
    const int gt   = blockIdx.x * blockDim.x + threadIdx.x;
    const int node = gt >> 5;
    const int lane = gt & 31;
    if (node >= N) return;

    const int start = g_rowptr[node];
    const int end   = g_rowptr[node + 1];
    const float dvi = g_dinv[node];

    float a0 = 0.f, a1 = 0.f, a2 = 0.f, a3 = 0.f;
    {
        const uint2 u = ((const uint2*)(g_bufh + (size_t)node * 64))[lane];
        const float2 f0 = __half22float2(u32_as_h2(u.x));
        const float2 f1 = __half22float2(u32_as_h2(u.y));
        a0 = fmaf(dvi, f0.x, a0); a1 = fmaf(dvi, f0.y, a1);
        a2 = fmaf(dvi, f1.x, a2); a3 = fmaf(dvi, f1.y, a3);
    }

    int k = start;
    for (; k + 4 <= end; k += 4) {
        const int j0 = g_src[k], j1 = g_src[k + 1], j2 = g_src[k + 2], j3 = g_src[k + 3];
        const float d0 = g_dinv[j0], d1 = g_dinv[j1], d2 = g_dinv[j2], d3 = g_dinv[j3];
        const uint2 u0 = ((const uint2*)(g_bufh + (size_t)j0 * 64))[lane];
        const uint2 u1 = ((const uint2*)(g_bufh + (size_t)j1 * 64))[lane];
        const uint2 u2 = ((const uint2*)(g_bufh + (size_t)j2 * 64))[lane];
        const uint2 u3 = ((const uint2*)(g_bufh + (size_t)j3 * 64))[lane];
        float2 f;
        f = __half22float2(u32_as_h2(u0.x)); a0 = fmaf(d0, f.x, a0); a1 = fmaf(d0, f.y, a1);
        f = __half22float2(u32_as_h2(u0.y)); a2 = fmaf(d0, f.x, a2); a3 = fmaf(d0, f.y, a3);
        f = __half22float2(u32_as_h2(u1.x)); a0 = fmaf(d1, f.x, a0); a1 = fmaf(d1, f.y, a1);
        f = __half22float2(u32_as_h2(u1.y)); a2 = fmaf(d1, f.x, a2); a3 = fmaf(d1, f.y, a3);
        f = __half22float2(u32_as_h2(u2.x)); a0 = fmaf(d2, f.x, a0); a1 = fmaf(d2, f.y, a1);
        f = __half22float2(u32_as_h2(u2.y)); a2 = fmaf(d2, f.x, a2); a3 = fmaf(d2, f.y, a3);
        f = __half22float2(u32_as_h2(u3.x)); a0 = fmaf(d3, f.x, a0); a1 = fmaf(d3, f.y, a1);
        f = __half22float2(u32_as_h2(u3.y)); a2 = fmaf(d3, f.x, a2); a3 = fmaf(d3, f.y, a3);
    }
    for (; k < end; k++) {
        const int j = g_src[k];
        const float dj = g_dinv[j];
        const uint2 u = ((const uint2*)(g_bufh + (size_t)j * 64))[lane];
        float2 f;
        f = __half22float2(u32_as_h2(u.x)); a0 = fmaf(dj, f.x, a0); a1 = fmaf(dj, f.y, a1);
        f = __half22float2(u32_as_h2(u.y)); a2 = fmaf(dj, f.x, a2); a3 = fmaf(dj, f.y, a3);
    }

    const float4 b = ((const float4*)bias)[lane];
    float4 r;
    r.x = a0 * dvi + b.x;
    r.y = a1 * dvi + b.y;
    r.z = a2 * dvi + b.z;
    r.w = a3 * dvi + b.w;
    ((float4*)(out + (size_t)node * D))[lane] = r;
}

// ---------------------------------------------------------------------------
extern "C" void kernel_launch(void* const* d_in, const int* in_sizes, int n_in,
                              void* d_out, int out_size)
{
    const float* x     = (const float*)d_in[0];
    const void*  edges = (const void*)d_in[1];
    const float* gamma = (const float*)d_in[2];
    const float* beta  = (const float*)d_in[3];
    const float* W     = (const float*)d_in[4];
    const float* bias  = (const float*)d_in[5];
    float*       out   = (float*)d_out;

    const int N = in_sizes[0] / D;
    const int E = in_sizes[1] / 2;
    const int nblk = (N + SCAN_B - 1) / SCAN_B;

    k_init<<<(N + 255) / 256, 256>>>(edges, N, N);
    k_hist<<<(E + 255) / 256, 256>>>(edges, E, N);
    k_scan1<<<nblk, SCAN_B>>>(N);
    k_scan2<<<1, MAX_BLK>>>(nblk);
    k_scan3<<<nblk, SCAN_B>>>(N, E);
    k_fill<<<(E + 255) / 256, 256>>>(edges, E, N);

    fused_ln_gemm_kernel<<<(N + 63) / 64, 256>>>(x, gamma, beta, W, N);

    k_aggr<<<(N * 32 + 255) / 256, 256>>>(out, bias, N);
}

// round 7
// speedup vs baseline: 1.1900x; 1.0303x over previous
#include <cuda_runtime.h>
#include <cuda_fp16.h>
#include <cstdint>

#define MAX_N   131072
#define MAX_E   1700000
#define D       128
#define SCAN_B  512
#define MAX_BLK 256   // MAX_N / SCAN_B

// ---- scratch (__device__ globals; no allocations allowed) ----
__device__ __align__(16) __half2 g_bufh[(size_t)MAX_N * 64];  // g = dinv*relu(LN(x))@W, fp16
__device__ float g_dinv[MAX_N];
__device__ int   g_cnt[MAX_N];
__device__ int   g_rowptr[MAX_N + 1];
__device__ int   g_cur[MAX_N];
__device__ int   g_blk[MAX_BLK];
__device__ int   g_src[MAX_E];
__device__ int   g_e64;          // 1 if edge_index is int64, 0 if int32

// ---------------------------------------------------------------------------
__device__ __forceinline__ unsigned long long fma2(unsigned long long a,
                                                   unsigned long long b,
                                                   unsigned long long c) {
    unsigned long long d;
    asm("fma.rn.f32x2 %0, %1, %2, %3;" : "=l"(d) : "l"(a), "l"(b), "l"(c));
    return d;
}
__device__ __forceinline__ unsigned long long pk2(float x) {  // (x, x) packed
    unsigned long long d;
    asm("mov.b64 %0, {%1, %1};" : "=l"(d) : "f"(x));
    return d;
}
__device__ __forceinline__ float lo32(unsigned long long u) {
    return __uint_as_float((unsigned)(u & 0xFFFFFFFFull));
}
__device__ __forceinline__ float hi32(unsigned long long u) {
    return __uint_as_float((unsigned)(u >> 32));
}
__device__ __forceinline__ unsigned h2_as_u32(__half2 h) {
    union { __half2 h; unsigned u; } cvt; cvt.h = h; return cvt.u;
}
__device__ __forceinline__ __half2 u32_as_h2(unsigned u) {
    union { unsigned u; __half2 h; } cvt; cvt.u = u; return cvt.h;
}

__device__ __forceinline__ int load_idx(const void* edges, long long i, int e64) {
    if (e64) return (int)((const long long*)edges)[i];
    return ((const int*)edges)[i];
}

// ---------------------------------------------------------------------------
// L1: zero g_cnt + parallel edge-dtype probe.
__global__ void k_init(const void* __restrict__ edges, int N, int n) {
    __shared__ int bad;
    const int i = blockIdx.x * blockDim.x + threadIdx.x;
    if (i < n) g_cnt[i] = 0;
    if (blockIdx.x == 0) {
        if (threadIdx.x == 0) bad = 0;
        __syncthreads();
        if (threadIdx.x < 64) {
            long long v = ((const long long*)edges)[threadIdx.x];
            if (v < 0 || v >= (long long)N) atomicOr(&bad, 1);
        }
        __syncthreads();
        if (threadIdx.x == 0) g_e64 = bad ? 0 : 1;
    }
}

// L2: histogram over edge targets
__global__ void k_hist(const void* __restrict__ edges, int E, int N) {
    int e = blockIdx.x * blockDim.x + threadIdx.x;
    if (e < E) {
        int c = load_idx(edges, (long long)E + e, g_e64);
        if ((unsigned)c < (unsigned)N) atomicAdd(&g_cnt[c], 1);
    }
}

// L3: per-block scan of g_cnt -> g_rowptr (block-local), totals -> g_blk, fused dinv.
__global__ void k_scan1(int n) {
    __shared__ int s[SCAN_B];
    const int tid = threadIdx.x;
    const int i   = blockIdx.x * SCAN_B + tid;
    const int v   = (i < n) ? g_cnt[i] : 0;
    if (i < n) g_dinv[i] = rsqrtf((float)(v + 1));   // +1 self loop
    s[tid] = v;
    __syncthreads();
    #pragma unroll
    for (int off = 1; off < SCAN_B; off <<= 1) {
        int t = (tid >= off) ? s[tid - off] : 0;
        __syncthreads();
        s[tid] += t;
        __syncthreads();
    }
    if (i < n) g_rowptr[i] = s[tid] - v;
    if (tid == SCAN_B - 1) g_blk[blockIdx.x] = s[tid];
}

// L4 (profiled slot): fused LayerNorm -> ReLU -> GEMM -> *dinv, fp16 into g_bufh.
__global__ void __launch_bounds__(256) fused_ln_gemm_kernel(
    const float* __restrict__ x,
    const float* __restrict__ gamma,
    const float* __restrict__ beta,
    const float* __restrict__ W, int N)
{
    __shared__ float a_s[128 * 72];   // k-major: a_s[k*72 + n], n in [0,64)
    const int tid  = threadIdx.x;
    const int warp = tid >> 5;
    const int lane = tid & 31;
    const int node0 = blockIdx.x * 64;

    // ---- Phase A: LayerNorm + ReLU into shared (k-major) ----
    #pragma unroll
    for (int rr = 0; rr < 8; rr++) {
        const int n = warp * 8 + rr;
        const int node = node0 + n;
        float v0 = 0.f, v1 = 0.f, v2 = 0.f, v3 = 0.f;
        if (node < N) {
            const float* xr = x + (size_t)node * D;
            v0 = xr[lane]; v1 = xr[lane + 32]; v2 = xr[lane + 64]; v3 = xr[lane + 96];
        }
        float s  = v0 + v1 + v2 + v3;
        float sq = v0 * v0 + v1 * v1 + v2 * v2 + v3 * v3;
        #pragma unroll
        for (int off = 16; off; off >>= 1) {
            s  += __shfl_xor_sync(0xFFFFFFFFu, s,  off);
            sq += __shfl_xor_sync(0xFFFFFFFFu, sq, off);
        }
        const float mu  = s * (1.0f / 128.0f);
        const float var = sq * (1.0f / 128.0f) - mu * mu;
        const float rs  = rsqrtf(var + 1e-5f);
        float t;
        t = fmaxf((v0 - mu) * rs * gamma[lane]      + beta[lane],      0.f); a_s[(lane)      * 72 + n] = t;
        t = fmaxf((v1 - mu) * rs * gamma[lane + 32] + beta[lane + 32], 0.f); a_s[(lane + 32) * 72 + n] = t;
        t = fmaxf((v2 - mu) * rs * gamma[lane + 64] + beta[lane + 64], 0.f); a_s[(lane + 64) * 72 + n] = t;
        t = fmaxf((v3 - mu) * rs * gamma[lane + 96] + beta[lane + 96], 0.f); a_s[(lane + 96) * 72 + n] = t;
    }
    __syncthreads();

    // ---- Phase B: packed fma.f32x2 GEMM ----
    const int cg = lane;
    const int nb = warp * 8;
    unsigned long long acc[4][4];
    #pragma unroll
    for (int p = 0; p < 4; p++)
        #pragma unroll
        for (int c = 0; c < 4; c++) acc[p][c] = 0ull;

    const float4* W4 = (const float4*)W;
    #pragma unroll 8
    for (int k = 0; k < 128; k++) {
        const float4 w = W4[k * 32 + cg];
        unsigned long long wp[4] = { pk2(w.x), pk2(w.y), pk2(w.z), pk2(w.w) };
        const double2* ad = (const double2*)&a_s[k * 72 + nb];
        const double2 a01 = ad[0];
        const double2 a23 = ad[1];
        unsigned long long ap[4] = {
            (unsigned long long)__double_as_longlong(a01.x),
            (unsigned long long)__double_as_longlong(a01.y),
            (unsigned long long)__double_as_longlong(a23.x),
            (unsigned long long)__double_as_longlong(a23.y)
        };
        #pragma unroll
        for (int p = 0; p < 4; p++)
            #pragma unroll
            for (int c = 0; c < 4; c++)
                acc[p][c] = fma2(ap[p], wp[c], acc[p][c]);
    }

    // ---- Epilogue: scale by dinv[node], fp16 store ----
    #pragma unroll
    for (int p = 0; p < 4; p++) {
        const int nA = node0 + nb + 2 * p;
        const int nB = nA + 1;
        if (nA < N) {
            const float dv = g_dinv[nA];
            __half2 h01 = __floats2half2_rn(lo32(acc[p][0]) * dv, lo32(acc[p][1]) * dv);
            __half2 h23 = __floats2half2_rn(lo32(acc[p][2]) * dv, lo32(acc[p][3]) * dv);
            uint2 u; u.x = h2_as_u32(h01); u.y = h2_as_u32(h23);
            ((uint2*)(g_bufh + (size_t)nA * 64))[cg] = u;
        }
        if (nB < N) {
            const float dv = g_dinv[nB];
            __half2 h01 = __floats2half2_rn(hi32(acc[p][0]) * dv, hi32(acc[p][1]) * dv);
            __half2 h23 = __floats2half2_rn(hi32(acc[p][2]) * dv, hi32(acc[p][3]) * dv);
            uint2 u; u.x = h2_as_u32(h01); u.y = h2_as_u32(h23);
            ((uint2*)(g_bufh + (size_t)nB * 64))[cg] = u;
        }
    }
}

// L5: parallel scan of block totals (single block)
__global__ void k_scan2(int nblk) {
    __shared__ int s[MAX_BLK];
    const int tid = threadIdx.x;
    const int v = (tid < nblk) ? g_blk[tid] : 0;
    s[tid] = v;
    __syncthreads();
    #pragma unroll
    for (int off = 1; off < MAX_BLK; off <<= 1) {
        int t = (tid >= off) ? s[tid - off] : 0;
        __syncthreads();
        s[tid] += t;
        __syncthreads();
    }
    if (tid < nblk) g_blk[tid] = s[tid] - v;   // exclusive
}

// L6: add block offsets; init cursors; set rowptr[N]
__global__ void k_scan3(int n, int E) {
    const int i = blockIdx.x * SCAN_B + threadIdx.x;
    if (i < n) {
        int r = g_rowptr[i] + g_blk[blockIdx.x];
        g_rowptr[i] = r;
        g_cur[i]    = r;
    }
    if (blockIdx.x == 0 && threadIdx.x == 0) g_rowptr[n] = E;
}

// L7: CSR fill
__global__ void k_fill(const void* __restrict__ edges, int E, int N) {
    int e = blockIdx.x * blockDim.x + threadIdx.x;
    if (e < E) {
        const int e64 = g_e64;
        int r = load_idx(edges, e, e64);
        int c = load_idx(edges, (long long)E + e, e64);
        if ((unsigned)c < (unsigned)N && (unsigned)r < (unsigned)N) {
            int pos = atomicAdd(&g_cur[c], 1);
            if (pos < MAX_E) g_src[pos] = r;
        }
    }
}

// L8: warp-per-node gather: out[i] = dinv[i]*(g[i] + sum_j g[j]) + bias
//     (g already includes the source-side dinv)
__global__ void __launch_bounds__(256) k_aggr(float* __restrict__ out,
                                              const float* __restrict__ bias, int N)
{
    const int gt   = blockIdx.x * blockDim.x + threadIdx.x;
    const int node = gt >> 5;
    const int lane = gt & 31;
    if (node >= N) return;

    const int start = g_rowptr[node];
    const int end   = g_rowptr[node + 1];

    float a0, a1, a2, a3;
    {
        const uint2 u = ((const uint2*)(g_bufh + (size_t)node * 64))[lane];
        const float2 f0 = __half22float2(u32_as_h2(u.x));
        const float2 f1 = __half22float2(u32_as_h2(u.y));
        a0 = f0.x; a1 = f0.y; a2 = f1.x; a3 = f1.y;
    }

    int k = start;
    for (; k + 4 <= end; k += 4) {
        const int j0 = g_src[k], j1 = g_src[k + 1], j2 = g_src[k + 2], j3 = g_src[k + 3];
        const uint2 u0 = ((const uint2*)(g_bufh + (size_t)j0 * 64))[lane];
        const uint2 u1 = ((const uint2*)(g_bufh + (size_t)j1 * 64))[lane];
        const uint2 u2 = ((const uint2*)(g_bufh + (size_t)j2 * 64))[lane];
        const uint2 u3 = ((const uint2*)(g_bufh + (size_t)j3 * 64))[lane];
        float2 f;
        f = __half22float2(u32_as_h2(u0.x)); a0 += f.x; a1 += f.y;
        f = __half22float2(u32_as_h2(u0.y)); a2 += f.x; a3 += f.y;
        f = __half22float2(u32_as_h2(u1.x)); a0 += f.x; a1 += f.y;
        f = __half22float2(u32_as_h2(u1.y)); a2 += f.x; a3 += f.y;
        f = __half22float2(u32_as_h2(u2.x)); a0 += f.x; a1 += f.y;
        f = __half22float2(u32_as_h2(u2.y)); a2 += f.x; a3 += f.y;
        f = __half22float2(u32_as_h2(u3.x)); a0 += f.x; a1 += f.y;
        f = __half22float2(u32_as_h2(u3.y)); a2 += f.x; a3 += f.y;
    }
    for (; k < end; k++) {
        const int j = g_src[k];
        const uint2 u = ((const uint2*)(g_bufh + (size_t)j * 64))[lane];
        float2 f;
        f = __half22float2(u32_as_h2(u.x)); a0 += f.x; a1 += f.y;
        f = __half22float2(u32_as_h2(u.y)); a2 += f.x; a3 += f.y;
    }

    const float dvi = g_dinv[node];
    const float4 b = ((const float4*)bias)[lane];
    float4 r;
    r.x = a0 * dvi + b.x;
    r.y = a1 * dvi + b.y;
    r.z = a2 * dvi + b.z;
    r.w = a3 * dvi + b.w;
    ((float4*)(out + (size_t)node * D))[lane] = r;
}

// ---------------------------------------------------------------------------
extern "C" void kernel_launch(void* const* d_in, const int* in_sizes, int n_in,
                              void* d_out, int out_size)
{
    const float* x     = (const float*)d_in[0];
    const void*  edges = (const void*)d_in[1];
    const float* gamma = (const float*)d_in[2];
    const float* beta  = (const float*)d_in[3];
    const float* W     = (const float*)d_in[4];
    const float* bias  = (const float*)d_in[5];
    float*       out   = (float*)d_out;

    const int N = in_sizes[0] / D;
    const int E = in_sizes[1] / 2;
    const int nblk = (N + SCAN_B - 1) / SCAN_B;

    k_init<<<(N + 255) / 256, 256>>>(edges, N, N);                 // launch 1
    k_hist<<<(E + 255) / 256, 256>>>(edges, E, N);                 // launch 2
    k_scan1<<<nblk, SCAN_B>>>(N);                                  // launch 3
    fused_ln_gemm_kernel<<<(N + 63) / 64, 256>>>(x, gamma, beta, W, N);  // launch 4 (profiled)
    k_scan2<<<1, MAX_BLK>>>(nblk);                                 // launch 5
    k_scan3<<<nblk, SCAN_B>>>(N, E);                               // launch 6
    k_fill<<<(E + 255) / 256, 256>>>(edges, E, N);                 // launch 7
    k_aggr<<<(N * 32 + 255) / 256, 256>>>(out, bias, N);           // launch 8
}

// round 8
// speedup vs baseline: 1.6870x; 1.4177x over previous
#include <cuda_runtime.h>
#include <cuda_fp16.h>
#include <cstdint>

#define MAX_N   131072
#define MAX_E   1700000
#define D       128
#define SCAN_B  512
#define MAX_BLK 256   // MAX_N / SCAN_B

// Shared layout for the MMA GEMM kernel (halves, padded rows: 136 = 128 + 8)
#define A_STRIDE 136
#define W_STRIDE 136
#define GEMM_SMEM_BYTES ((64 * A_STRIDE + 128 * W_STRIDE) * 2)

// ---- scratch (__device__ globals; no allocations allowed) ----
__device__ __align__(16) __half2 g_bufh[(size_t)MAX_N * 64];  // g = dinv*relu(LN(x))@W, fp16
__device__ float g_dinv[MAX_N];
__device__ int   g_cnt[MAX_N];
__device__ int   g_rowptr[MAX_N + 1];
__device__ int   g_cur[MAX_N];
__device__ int   g_blk[MAX_BLK];
__device__ int   g_src[MAX_E];
__device__ int   g_e64;          // 1 if edge_index is int64, 0 if int32

// ---------------------------------------------------------------------------
__device__ __forceinline__ unsigned h2_as_u32(__half2 h) {
    union { __half2 h; unsigned u; } cvt; cvt.h = h; return cvt.u;
}
__device__ __forceinline__ __half2 u32_as_h2(unsigned u) {
    union { unsigned u; __half2 h; } cvt; cvt.u = u; return cvt.h;
}
__device__ __forceinline__ int load_idx(const void* edges, long long i, int e64) {
    if (e64) return (int)((const long long*)edges)[i];
    return ((const int*)edges)[i];
}
__device__ __forceinline__ uint32_t smem_u32(const void* p) {
    return (uint32_t)__cvta_generic_to_shared(p);
}

// ---------------------------------------------------------------------------
// L1: zero g_cnt + parallel edge-dtype probe.
__global__ void k_init(const void* __restrict__ edges, int N, int n) {
    __shared__ int bad;
    const int i = blockIdx.x * blockDim.x + threadIdx.x;
    if (i < n) g_cnt[i] = 0;
    if (blockIdx.x == 0) {
        if (threadIdx.x == 0) bad = 0;
        __syncthreads();
        if (threadIdx.x < 64) {
            long long v = ((const long long*)edges)[threadIdx.x];
            if (v < 0 || v >= (long long)N) atomicOr(&bad, 1);
        }
        __syncthreads();
        if (threadIdx.x == 0) g_e64 = bad ? 0 : 1;
    }
}

// L2: histogram over edge targets
__global__ void k_hist(const void* __restrict__ edges, int E, int N) {
    int e = blockIdx.x * blockDim.x + threadIdx.x;
    if (e < E) {
        int c = load_idx(edges, (long long)E + e, g_e64);
        if ((unsigned)c < (unsigned)N) atomicAdd(&g_cnt[c], 1);
    }
}

// L3: per-block scan of g_cnt -> g_rowptr, totals -> g_blk, fused dinv.
__global__ void k_scan1(int n) {
    __shared__ int s[SCAN_B];
    const int tid = threadIdx.x;
    const int i   = blockIdx.x * SCAN_B + tid;
    const int v   = (i < n) ? g_cnt[i] : 0;
    if (i < n) g_dinv[i] = rsqrtf((float)(v + 1));   // +1 self loop
    s[tid] = v;
    __syncthreads();
    #pragma unroll
    for (int off = 1; off < SCAN_B; off <<= 1) {
        int t = (tid >= off) ? s[tid - off] : 0;
        __syncthreads();
        s[tid] += t;
        __syncthreads();
    }
    if (i < n) g_rowptr[i] = s[tid] - v;
    if (tid == SCAN_B - 1) g_blk[blockIdx.x] = s[tid];
}

// ---------------------------------------------------------------------------
// L4 (profiled slot): fused LayerNorm -> ReLU -> HMMA GEMM -> *dinv, fp16 out.
// 256 threads, 64 nodes/block. mma.sync.m16n8k16 fp16 -> fp32.
__global__ void __launch_bounds__(256) fused_ln_gemm_kernel(
    const float* __restrict__ x,
    const float* __restrict__ gamma,
    const float* __restrict__ beta,
    const float* __restrict__ W, int N)
{
    extern __shared__ __align__(16) __half smem[];
    __half* A_s = smem;                    // [64][A_STRIDE]
    __half* W_s = smem + 64 * A_STRIDE;    // [128][W_STRIDE]

    const int tid  = threadIdx.x;
    const int warp = tid >> 5;
    const int lane = tid & 31;
    const int node0 = blockIdx.x * 64;

    // ---- Phase 0: convert W (fp32 row-major [k][n]) to fp16 W_s ----
    {
        const float4* W4 = (const float4*)W;
        #pragma unroll
        for (int i = tid; i < 128 * 32; i += 256) {   // 128 rows x 32 float4
            const int row = i >> 5;
            const int c4  = i & 31;
            const float4 w = W4[i];
            __half2 h0 = __floats2half2_rn(w.x, w.y);
            __half2 h1 = __floats2half2_rn(w.z, w.w);
            uint2 u; u.x = h2_as_u32(h0); u.y = h2_as_u32(h1);
            *(uint2*)&W_s[row * W_STRIDE + c4 * 4] = u;
        }
    }

    // ---- Phase A: LayerNorm + ReLU into A_s (fp16, row-major) ----
    #pragma unroll
    for (int rr = 0; rr < 8; rr++) {
        const int n = warp * 8 + rr;
        const int node = node0 + n;
        float v0 = 0.f, v1 = 0.f, v2 = 0.f, v3 = 0.f;
        if (node < N) {
            const float* xr = x + (size_t)node * D;
            v0 = xr[lane]; v1 = xr[lane + 32]; v2 = xr[lane + 64]; v3 = xr[lane + 96];
        }
        float s  = v0 + v1 + v2 + v3;
        float sq = v0 * v0 + v1 * v1 + v2 * v2 + v3 * v3;
        #pragma unroll
        for (int off = 16; off; off >>= 1) {
            s  += __shfl_xor_sync(0xFFFFFFFFu, s,  off);
            sq += __shfl_xor_sync(0xFFFFFFFFu, sq, off);
        }
        const float mu  = s * (1.0f / 128.0f);
        const float var = sq * (1.0f / 128.0f) - mu * mu;
        const float rs  = rsqrtf(var + 1e-5f);
        __half* ar = &A_s[n * A_STRIDE];
        ar[lane]      = __float2half(fmaxf((v0 - mu) * rs * gamma[lane]      + beta[lane],      0.f));
        ar[lane + 32] = __float2half(fmaxf((v1 - mu) * rs * gamma[lane + 32] + beta[lane + 32], 0.f));
        ar[lane + 64] = __float2half(fmaxf((v2 - mu) * rs * gamma[lane + 64] + beta[lane + 64], 0.f));
        ar[lane + 96] = __float2half(fmaxf((v3 - mu) * rs * gamma[lane + 96] + beta[lane + 96], 0.f));
    }
    __syncthreads();

    // ---- Phase B: HMMA. warp -> (mtile = warp>>1, nhalf = (warp&1)*64) ----
    const int mtile = warp >> 1;
    const int nhalf = (warp & 1) * 64;
    const int m0 = mtile * 16;

    float acc[8][4];
    #pragma unroll
    for (int nn = 0; nn < 8; nn++)
        #pragma unroll
        for (int c = 0; c < 4; c++) acc[nn][c] = 0.f;

    // ldmatrix addresses
    const uint32_t a_addr0 = smem_u32(&A_s[(m0 + (lane & 15)) * A_STRIDE + (lane >> 4) * 8]);
    const uint32_t b_addr0 = smem_u32(&W_s[(lane & 15) * W_STRIDE + nhalf]);

    #pragma unroll
    for (int kk = 0; kk < 8; kk++) {
        uint32_t a0, a1, a2, a3;
        asm volatile("ldmatrix.sync.aligned.m8n8.x4.shared.b16 {%0,%1,%2,%3}, [%4];"
                     : "=r"(a0), "=r"(a1), "=r"(a2), "=r"(a3)
                     : "r"(a_addr0 + kk * 32));
        const uint32_t b_k = b_addr0 + kk * (16 * W_STRIDE * 2);
        #pragma unroll
        for (int nn = 0; nn < 8; nn++) {
            uint32_t b0, b1;
            asm volatile("ldmatrix.sync.aligned.m8n8.x2.trans.shared.b16 {%0,%1}, [%2];"
                         : "=r"(b0), "=r"(b1)
                         : "r"(b_k + nn * 16));
            asm volatile("mma.sync.aligned.m16n8k16.row.col.f32.f16.f16.f32 "
                         "{%0,%1,%2,%3}, {%4,%5,%6,%7}, {%8,%9}, {%0,%1,%2,%3};"
                         : "+f"(acc[nn][0]), "+f"(acc[nn][1]), "+f"(acc[nn][2]), "+f"(acc[nn][3])
                         : "r"(a0), "r"(a1), "r"(a2), "r"(a3), "r"(b0), "r"(b1));
        }
    }

    // ---- Epilogue: scale by dinv[node], fp16 store to g_bufh ----
    const int group = lane >> 2;        // 0..7
    const int qp    = lane & 3;         // 0..3
    const int r0 = node0 + m0 + group;
    const int r1 = r0 + 8;
    const float dv0 = (r0 < N) ? g_dinv[r0] : 0.f;
    const float dv1 = (r1 < N) ? g_dinv[r1] : 0.f;
    #pragma unroll
    for (int nn = 0; nn < 8; nn++) {
        const int col2 = (nhalf >> 1) + nn * 4 + qp;   // half2 index within row
        if (r0 < N)
            g_bufh[(size_t)r0 * 64 + col2] = __floats2half2_rn(acc[nn][0] * dv0, acc[nn][1] * dv0);
        if (r1 < N)
            g_bufh[(size_t)r1 * 64 + col2] = __floats2half2_rn(acc[nn][2] * dv1, acc[nn][3] * dv1);
    }
}

// ---------------------------------------------------------------------------
// L5: parallel scan of block totals (single block)
__global__ void k_scan2(int nblk) {
    __shared__ int s[MAX_BLK];
    const int tid = threadIdx.x;
    const int v = (tid < nblk) ? g_blk[tid] : 0;
    s[tid] = v;
    __syncthreads();
    #pragma unroll
    for (int off = 1; off < MAX_BLK; off <<= 1) {
        int t = (tid >= off) ? s[tid - off] : 0;
        __syncthreads();
        s[tid] += t;
        __syncthreads();
    }
    if (tid < nblk) g_blk[tid] = s[tid] - v;   // exclusive
}

// L6: add block offsets; init cursors; set rowptr[N]
__global__ void k_scan3(int n, int E) {
    const int i = blockIdx.x * SCAN_B + threadIdx.x;
    if (i < n) {
        int r = g_rowptr[i] + g_blk[blockIdx.x];
        g_rowptr[i] = r;
        g_cur[i]    = r;
    }
    if (blockIdx.x == 0 && threadIdx.x == 0) g_rowptr[n] = E;
}

// L7: CSR fill
__global__ void k_fill(const void* __restrict__ edges, int E, int N) {
    int e = blockIdx.x * blockDim.x + threadIdx.x;
    if (e < E) {
        const int e64 = g_e64;
        int r = load_idx(edges, e, e64);
        int c = load_idx(edges, (long long)E + e, e64);
        if ((unsigned)c < (unsigned)N && (unsigned)r < (unsigned)N) {
            int pos = atomicAdd(&g_cur[c], 1);
            if (pos < MAX_E) g_src[pos] = r;
        }
    }
}

// L8: warp-per-node gather: out[i] = dinv[i]*(g[i] + sum_j g[j]) + bias
__global__ void __launch_bounds__(256) k_aggr(float* __restrict__ out,
                                              const float* __restrict__ bias, int N)
{
    const int gt   = blockIdx.x * blockDim.x + threadIdx.x;
    const int node = gt >> 5;
    const int lane = gt & 31;
    if (node >= N) return;

    const int start = g_rowptr[node];
    const int end   = g_rowptr[node + 1];

    float a0, a1, a2, a3;
    {
        const uint2 u = ((const uint2*)(g_bufh + (size_t)node * 64))[lane];
        const float2 f0 = __half22float2(u32_as_h2(u.x));
        const float2 f1 = __half22float2(u32_as_h2(u.y));
        a0 = f0.x; a1 = f0.y; a2 = f1.x; a3 = f1.y;
    }

    int k = start;
    for (; k + 4 <= end; k += 4) {
        const int j0 = g_src[k], j1 = g_src[k + 1], j2 = g_src[k + 2], j3 = g_src[k + 3];
        const uint2 u0 = ((const uint2*)(g_bufh + (size_t)j0 * 64))[lane];
        const uint2 u1 = ((const uint2*)(g_bufh + (size_t)j1 * 64))[lane];
        const uint2 u2 = ((const uint2*)(g_bufh + (size_t)j2 * 64))[lane];
        const uint2 u3 = ((const uint2*)(g_bufh + (size_t)j3 * 64))[lane];
        float2 f;
        f = __half22float2(u32_as_h2(u0.x)); a0 += f.x; a1 += f.y;
        f = __half22float2(u32_as_h2(u0.y)); a2 += f.x; a3 += f.y;
        f = __half22float2(u32_as_h2(u1.x)); a0 += f.x; a1 += f.y;
        f = __half22float2(u32_as_h2(u1.y)); a2 += f.x; a3 += f.y;
        f = __half22float2(u32_as_h2(u2.x)); a0 += f.x; a1 += f.y;
        f = __half22float2(u32_as_h2(u2.y)); a2 += f.x; a3 += f.y;
        f = __half22float2(u32_as_h2(u3.x)); a0 += f.x; a1 += f.y;
        f = __half22float2(u32_as_h2(u3.y)); a2 += f.x; a3 += f.y;
    }
    for (; k < end; k++) {
        const int j = g_src[k];
        const uint2 u = ((const uint2*)(g_bufh + (size_t)j * 64))[lane];
        float2 f;
        f = __half22float2(u32_as_h2(u.x)); a0 += f.x; a1 += f.y;
        f = __half22float2(u32_as_h2(u.y)); a2 += f.x; a3 += f.y;
    }

    const float dvi = g_dinv[node];
    const float4 b = ((const float4*)bias)[lane];
    float4 r;
    r.x = a0 * dvi + b.x;
    r.y = a1 * dvi + b.y;
    r.z = a2 * dvi + b.z;
    r.w = a3 * dvi + b.w;
    ((float4*)(out + (size_t)node * D))[lane] = r;
}

// ---------------------------------------------------------------------------
extern "C" void kernel_launch(void* const* d_in, const int* in_sizes, int n_in,
                              void* d_out, int out_size)
{
    const float* x     = (const float*)d_in[0];
    const void*  edges = (const void*)d_in[1];
    const float* gamma = (const float*)d_in[2];
    const float* beta  = (const float*)d_in[3];
    const float* W     = (const float*)d_in[4];
    const float* bias  = (const float*)d_in[5];
    float*       out   = (float*)d_out;

    const int N = in_sizes[0] / D;
    const int E = in_sizes[1] / 2;
    const int nblk = (N + SCAN_B - 1) / SCAN_B;

    static int smem_set = 0;
    if (!smem_set) {
        cudaFuncSetAttribute(fused_ln_gemm_kernel,
                             cudaFuncAttributeMaxDynamicSharedMemorySize,
                             GEMM_SMEM_BYTES);
        smem_set = 1;
    }

    k_init<<<(N + 255) / 256, 256>>>(edges, N, N);                 // launch 1
    k_hist<<<(E + 255) / 256, 256>>>(edges, E, N);                 // launch 2
    k_scan1<<<nblk, SCAN_B>>>(N);                                  // launch 3
    fused_ln_gemm_kernel<<<(N + 63) / 64, 256, GEMM_SMEM_BYTES>>>( // launch 4 (profiled)
        x, gamma, beta, W, N);
    k_scan2<<<1, MAX_BLK>>>(nblk);                                 // launch 5
    k_scan3<<<nblk, SCAN_B>>>(N, E);                               // launch 6
    k_fill<<<(E + 255) / 256, 256>>>(edges, E, N);                 // launch 7
    k_aggr<<<(N * 32 + 255) / 256, 256>>>(out, bias, N);           // launch 8
}

// round 9
// speedup vs baseline: 1.7208x; 1.0200x over previous
#include <cuda_runtime.h>
#include <cuda_fp16.h>
#include <cstdint>

#define MAX_N   131072
#define MAX_E   1700000
#define D       128
#define SCAN_B  512
#define MAX_BLK 256   // MAX_N / SCAN_B

// Shared layout for the MMA GEMM kernel (halves, padded rows: 136 = 128 + 8)
#define A_STRIDE 136
#define W_STRIDE 136
#define GEMM_SMEM_BYTES ((64 * A_STRIDE + 128 * W_STRIDE) * 2)

// ---- scratch (__device__ globals; no allocations allowed) ----
__device__ __align__(16) __half2 g_bufh[(size_t)MAX_N * 64];  // g = dinv*relu(LN(x))@W, fp16
__device__ __align__(16) __half2 g_Wh2[64 * 128];             // W in fp16, row-major [k][n]
__device__ float g_dinv[MAX_N];
__device__ int   g_cnt[MAX_N];
__device__ int   g_rowptr[MAX_N + 1];
__device__ int   g_cur[MAX_N];
__device__ int   g_blk[MAX_BLK];
__device__ int   g_src[MAX_E];
__device__ int   g_e64;          // 1 if edge_index is int64, 0 if int32
__device__ int   g_tick;         // scan1 last-block ticket

// ---------------------------------------------------------------------------
__device__ __forceinline__ unsigned h2_as_u32(__half2 h) {
    union { __half2 h; unsigned u; } cvt; cvt.h = h; return cvt.u;
}
__device__ __forceinline__ __half2 u32_as_h2(unsigned u) {
    union { unsigned u; __half2 h; } cvt; cvt.u = u; return cvt.h;
}
__device__ __forceinline__ int load_idx(const void* edges, long long i, int e64) {
    if (e64) return (int)((const long long*)edges)[i];
    return ((const int*)edges)[i];
}
__device__ __forceinline__ uint32_t smem_u32(const void* p) {
    return (uint32_t)__cvta_generic_to_shared(p);
}

// ---------------------------------------------------------------------------
// L1: zero g_cnt + dtype probe (block 0) + W->fp16 conversion (blocks 1..32)
//     + reset scan ticket.
__global__ void k_init(const void* __restrict__ edges, const float* __restrict__ W,
                       int N, int n) {
    __shared__ int bad;
    const int i = blockIdx.x * blockDim.x + threadIdx.x;
    if (i < n) g_cnt[i] = 0;
    if (blockIdx.x == 0) {
        if (threadIdx.x == 0) { bad = 0; g_tick = 0; }
        __syncthreads();
        if (threadIdx.x < 64) {
            long long v = ((const long long*)edges)[threadIdx.x];
            if (v < 0 || v >= (long long)N) atomicOr(&bad, 1);
        }
        __syncthreads();
        if (threadIdx.x == 0) g_e64 = bad ? 0 : 1;
    } else if (blockIdx.x <= 32) {
        const int j = (blockIdx.x - 1) * 256 + threadIdx.x;  // [0, 8192)
        const float2 w = ((const float2*)W)[j];
        g_Wh2[j] = __floats2half2_rn(w.x, w.y);
    }
}

// L2: histogram over edge targets
__global__ void k_hist(const void* __restrict__ edges, int E, int N) {
    int e = blockIdx.x * blockDim.x + threadIdx.x;
    if (e < E) {
        int c = load_idx(edges, (long long)E + e, g_e64);
        if ((unsigned)c < (unsigned)N) atomicAdd(&g_cnt[c], 1);
    }
}

// L3: per-block scan of g_cnt -> g_rowptr + dinv; last block scans block totals.
__global__ void k_scan1(int n, int nblk) {
    __shared__ int s[SCAN_B];
    __shared__ int isLast;
    const int tid = threadIdx.x;
    const int i   = blockIdx.x * SCAN_B + tid;
    const int v   = (i < n) ? g_cnt[i] : 0;
    if (i < n) g_dinv[i] = rsqrtf((float)(v + 1));   // +1 self loop
    s[tid] = v;
    __syncthreads();
    #pragma unroll
    for (int off = 1; off < SCAN_B; off <<= 1) {
        int t = (tid >= off) ? s[tid - off] : 0;
        __syncthreads();
        s[tid] += t;
        __syncthreads();
    }
    if (i < n) g_rowptr[i] = s[tid] - v;
    if (tid == SCAN_B - 1) g_blk[blockIdx.x] = s[tid];

    // last-block: exclusive scan of block totals (replaces k_scan2)
    __threadfence();
    if (tid == 0) isLast = (atomicAdd(&g_tick, 1) == nblk - 1) ? 1 : 0;
    __syncthreads();
    if (isLast) {
        const int bv = (tid < nblk) ? g_blk[tid] : 0;
        s[tid] = (tid < MAX_BLK) ? bv : 0;
        __syncthreads();
        #pragma unroll
        for (int off = 1; off < MAX_BLK; off <<= 1) {
            int t = (tid >= off && tid < MAX_BLK) ? s[tid - off] : 0;
            __syncthreads();
            if (tid < MAX_BLK) s[tid] += t;
            __syncthreads();
        }
        if (tid < nblk) g_blk[tid] = s[tid] - bv;   // exclusive
    }
}

// ---------------------------------------------------------------------------
// L4 (profiled slot): fused LayerNorm -> ReLU -> HMMA GEMM -> *dinv, fp16 out.
// 256 threads, 64 nodes/block. Warp tile 32x32 (2 mtiles x 4 n8-tiles).
__global__ void __launch_bounds__(256) fused_ln_gemm_kernel(
    const float* __restrict__ x,
    const float* __restrict__ gamma,
    const float* __restrict__ beta,
    int N)
{
    extern __shared__ __align__(16) __half smem[];
    __half* A_s = smem;                    // [64][A_STRIDE]
    __half* W_s = smem + 64 * A_STRIDE;    // [128][W_STRIDE]

    const int tid  = threadIdx.x;
    const int warp = tid >> 5;
    const int lane = tid & 31;
    const int node0 = blockIdx.x * 64;

    // ---- Phase 0: stage fp16 W into shared ----
    {
        const uint4* src = (const uint4*)g_Wh2;     // 2048 uint4 (8 halves each)
        #pragma unroll
        for (int i = tid; i < 2048; i += 256) {
            const int row = i >> 4;
            const int c8  = i & 15;
            *(uint4*)&W_s[row * W_STRIDE + c8 * 8] = src[i];
        }
    }

    // ---- Phase A: LayerNorm + ReLU into A_s (fp16, row-major) ----
    #pragma unroll
    for (int rr = 0; rr < 8; rr++) {
        const int n = warp * 8 + rr;
        const int node = node0 + n;
        float v0 = 0.f, v1 = 0.f, v2 = 0.f, v3 = 0.f;
        if (node < N) {
            const float* xr = x + (size_t)node * D;
            v0 = xr[lane]; v1 = xr[lane + 32]; v2 = xr[lane + 64]; v3 = xr[lane + 96];
        }
        float s  = v0 + v1 + v2 + v3;
        float sq = v0 * v0 + v1 * v1 + v2 * v2 + v3 * v3;
        #pragma unroll
        for (int off = 16; off; off >>= 1) {
            s  += __shfl_xor_sync(0xFFFFFFFFu, s,  off);
            sq += __shfl_xor_sync(0xFFFFFFFFu, sq, off);
        }
        const float mu  = s * (1.0f / 128.0f);
        const float var = sq * (1.0f / 128.0f) - mu * mu;
        const float rs  = rsqrtf(var + 1e-5f);
        __half* ar = &A_s[n * A_STRIDE];
        ar[lane]      = __float2half(fmaxf((v0 - mu) * rs * gamma[lane]      + beta[lane],      0.f));
        ar[lane + 32] = __float2half(fmaxf((v1 - mu) * rs * gamma[lane + 32] + beta[lane + 32], 0.f));
        ar[lane + 64] = __float2half(fmaxf((v2 - mu) * rs * gamma[lane + 64] + beta[lane + 64], 0.f));
        ar[lane + 96] = __float2half(fmaxf((v3 - mu) * rs * gamma[lane + 96] + beta[lane + 96], 0.f));
    }
    __syncthreads();

    // ---- Phase B: HMMA. warp tile 32x32: wm = warp>>2, wn = warp&3 ----
    const int wm = warp >> 2;          // 0..1 -> rows [wm*32, wm*32+32)
    const int wn = warp & 3;           // 0..3 -> cols [wn*32, wn*32+32)

    float acc[2][4][4];
    #pragma unroll
    for (int mt = 0; mt < 2; mt++)
        #pragma unroll
        for (int nn = 0; nn < 4; nn++)
            #pragma unroll
            for (int c = 0; c < 4; c++) acc[mt][nn][c] = 0.f;

    const uint32_t a_addr0 = smem_u32(&A_s[(wm * 32 + (lane & 15)) * A_STRIDE + (lane >> 4) * 8]);
    const uint32_t a_addr1 = a_addr0 + 16 * A_STRIDE * 2;
    const uint32_t b_addr0 = smem_u32(&W_s[(lane & 15) * W_STRIDE + wn * 32]);

    #pragma unroll
    for (int kk = 0; kk < 8; kk++) {
        uint32_t b0[4], b1[4];
        const uint32_t b_k = b_addr0 + kk * (16 * W_STRIDE * 2);
        #pragma unroll
        for (int nn = 0; nn < 4; nn++) {
            asm volatile("ldmatrix.sync.aligned.m8n8.x2.trans.shared.b16 {%0,%1}, [%2];"
                         : "=r"(b0[nn]), "=r"(b1[nn])
                         : "r"(b_k + nn * 16));
        }
        uint32_t a[2][4];
        asm volatile("ldmatrix.sync.aligned.m8n8.x4.shared.b16 {%0,%1,%2,%3}, [%4];"
                     : "=r"(a[0][0]), "=r"(a[0][1]), "=r"(a[0][2]), "=r"(a[0][3])
                     : "r"(a_addr0 + kk * 32));
        asm volatile("ldmatrix.sync.aligned.m8n8.x4.shared.b16 {%0,%1,%2,%3}, [%4];"
                     : "=r"(a[1][0]), "=r"(a[1][1]), "=r"(a[1][2]), "=r"(a[1][3])
                     : "r"(a_addr1 + kk * 32));
        #pragma unroll
        for (int mt = 0; mt < 2; mt++)
            #pragma unroll
            for (int nn = 0; nn < 4; nn++)
                asm volatile("mma.sync.aligned.m16n8k16.row.col.f32.f16.f16.f32 "
                             "{%0,%1,%2,%3}, {%4,%5,%6,%7}, {%8,%9}, {%0,%1,%2,%3};"
                             : "+f"(acc[mt][nn][0]), "+f"(acc[mt][nn][1]),
                               "+f"(acc[mt][nn][2]), "+f"(acc[mt][nn][3])
                             : "r"(a[mt][0]), "r"(a[mt][1]), "r"(a[mt][2]), "r"(a[mt][3]),
                               "r"(b0[nn]), "r"(b1[nn]));
    }

    // ---- Epilogue: scale by dinv[node], fp16 store to g_bufh ----
    const int group = lane >> 2;        // 0..7
    const int qp    = lane & 3;         // 0..3
    #pragma unroll
    for (int mt = 0; mt < 2; mt++) {
        const int r0 = node0 + wm * 32 + mt * 16 + group;
        const int r1 = r0 + 8;
        const float dv0 = (r0 < N) ? g_dinv[r0] : 0.f;
        const float dv1 = (r1 < N) ? g_dinv[r1] : 0.f;
        #pragma unroll
        for (int nn = 0; nn < 4; nn++) {
            const int col2 = wn * 16 + nn * 4 + qp;   // half2 index within row
            if (r0 < N)
                g_bufh[(size_t)r0 * 64 + col2] =
                    __floats2half2_rn(acc[mt][nn][0] * dv0, acc[mt][nn][1] * dv0);
            if (r1 < N)
                g_bufh[(size_t)r1 * 64 + col2] =
                    __floats2half2_rn(acc[mt][nn][2] * dv1, acc[mt][nn][3] * dv1);
        }
    }
}

// ---------------------------------------------------------------------------
// L5: add block offsets; init cursors; set rowptr[N]
__global__ void k_scan3(int n, int E) {
    const int i = blockIdx.x * SCAN_B + threadIdx.x;
    if (i < n) {
        int r = g_rowptr[i] + g_blk[blockIdx.x];
        g_rowptr[i] = r;
        g_cur[i]    = r;
    }
    if (blockIdx.x == 0 && threadIdx.x == 0) g_rowptr[n] = E;
}

// L6: CSR fill
__global__ void k_fill(const void* __restrict__ edges, int E, int N) {
    int e = blockIdx.x * blockDim.x + threadIdx.x;
    if (e < E) {
        const int e64 = g_e64;
        int r = load_idx(edges, e, e64);
        int c = load_idx(edges, (long long)E + e, e64);
        if ((unsigned)c < (unsigned)N && (unsigned)r < (unsigned)N) {
            int pos = atomicAdd(&g_cur[c], 1);
            if (pos < MAX_E) g_src[pos] = r;
        }
    }
}

// L7: warp-per-node gather: out[i] = dinv[i]*(g[i] + sum_j g[j]) + bias
__global__ void __launch_bounds__(256) k_aggr(float* __restrict__ out,
                                              const float* __restrict__ bias, int N)
{
    const int gt   = blockIdx.x * blockDim.x + threadIdx.x;
    const int node = gt >> 5;
    const int lane = gt & 31;
    if (node >= N) return;

    const int start = g_rowptr[node];
    const int end   = g_rowptr[node + 1];

    float a0, a1, a2, a3;
    {
        const uint2 u = ((const uint2*)(g_bufh + (size_t)node * 64))[lane];
        const float2 f0 = __half22float2(u32_as_h2(u.x));
        const float2 f1 = __half22float2(u32_as_h2(u.y));
        a0 = f0.x; a1 = f0.y; a2 = f1.x; a3 = f1.y;
    }

    int k = start;
    for (; k + 4 <= end; k += 4) {
        const int j0 = g_src[k], j1 = g_src[k + 1], j2 = g_src[k + 2], j3 = g_src[k + 3];
        const uint2 u0 = ((const uint2*)(g_bufh + (size_t)j0 * 64))[lane];
        const uint2 u1 = ((const uint2*)(g_bufh + (size_t)j1 * 64))[lane];
        const uint2 u2 = ((const uint2*)(g_bufh + (size_t)j2 * 64))[lane];
        const uint2 u3 = ((const uint2*)(g_bufh + (size_t)j3 * 64))[lane];
        float2 f;
        f = __half22float2(u32_as_h2(u0.x)); a0 += f.x; a1 += f.y;
        f = __half22float2(u32_as_h2(u0.y)); a2 += f.x; a3 += f.y;
        f = __half22float2(u32_as_h2(u1.x)); a0 += f.x; a1 += f.y;
        f = __half22float2(u32_as_h2(u1.y)); a2 += f.x; a3 += f.y;
        f = __half22float2(u32_as_h2(u2.x)); a0 += f.x; a1 += f.y;
        f = __half22float2(u32_as_h2(u2.y)); a2 += f.x; a3 += f.y;
        f = __half22float2(u32_as_h2(u3.x)); a0 += f.x; a1 += f.y;
        f = __half22float2(u32_as_h2(u3.y)); a2 += f.x; a3 += f.y;
    }
    for (; k < end; k++) {
        const int j = g_src[k];
        const uint2 u = ((const uint2*)(g_bufh + (size_t)j * 64))[lane];
        float2 f;
        f = __half22float2(u32_as_h2(u.x)); a0 += f.x; a1 += f.y;
        f = __half22float2(u32_as_h2(u.y)); a2 += f.x; a3 += f.y;
    }

    const float dvi = g_dinv[node];
    const float4 b = ((const float4*)bias)[lane];
    float4 r;
    r.x = a0 * dvi + b.x;
    r.y = a1 * dvi + b.y;
    r.z = a2 * dvi + b.z;
    r.w = a3 * dvi + b.w;
    ((float4*)(out + (size_t)node * D))[lane] = r;
}

// ---------------------------------------------------------------------------
extern "C" void kernel_launch(void* const* d_in, const int* in_sizes, int n_in,
                              void* d_out, int out_size)
{
    const float* x     = (const float*)d_in[0];
    const void*  edges = (const void*)d_in[1];
    const float* gamma = (const float*)d_in[2];
    const float* beta  = (const float*)d_in[3];
    const float* W     = (const float*)d_in[4];
    const float* bias  = (const float*)d_in[5];
    float*       out   = (float*)d_out;

    const int N = in_sizes[0] / D;
    const int E = in_sizes[1] / 2;
    const int nblk = (N + SCAN_B - 1) / SCAN_B;

    static int smem_set = 0;
    if (!smem_set) {
        cudaFuncSetAttribute(fused_ln_gemm_kernel,
                             cudaFuncAttributeMaxDynamicSharedMemorySize,
                             GEMM_SMEM_BYTES);
        smem_set = 1;
    }

    k_init<<<(N + 255) / 256, 256>>>(edges, W, N, N);              // launch 1
    k_hist<<<(E + 255) / 256, 256>>>(edges, E, N);                 // launch 2
    k_scan1<<<nblk, SCAN_B>>>(N, nblk);                            // launch 3
    fused_ln_gemm_kernel<<<(N + 63) / 64, 256, GEMM_SMEM_BYTES>>>( // launch 4 (profiled)
        x, gamma, beta, N);
    k_scan3<<<nblk, SCAN_B>>>(N, E);                               // launch 5
    k_fill<<<(E + 255) / 256, 256>>>(edges, E, N);                 // launch 6
    k_aggr<<<(N * 32 + 255) / 256, 256>>>(out, bias, N);           // launch 7
}

// round 10
// speedup vs baseline: 1.7890x; 1.0396x over previous
#include <cuda_runtime.h>
#include <cuda_fp16.h>
#include <cstdint>

#define MAX_N   131072
#define MAX_E   1700000
#define D       128
#define SCAN_B  512
#define MAX_BLK 256   // MAX_N / SCAN_B

// Shared layout for the MMA GEMM kernel (halves, padded rows: 136 = 128 + 8)
#define A_STRIDE 136
#define W_STRIDE 136
#define GEMM_SMEM_BYTES ((64 * A_STRIDE + 128 * W_STRIDE) * 2)

// ---- scratch (__device__ globals; no allocations allowed) ----
__device__ __align__(16) __half2 g_bufh[(size_t)MAX_N * 64];  // g = dinv*relu(LN(x))@W, fp16
__device__ __align__(16) __half2 g_Wh2[64 * 128];             // W in fp16, row-major [k][n]
__device__ float g_dinv[MAX_N];
__device__ int   g_cnt[MAX_N];
__device__ int   g_rowptr[MAX_N + 1];
__device__ int   g_cur[MAX_N];
__device__ int   g_blk[MAX_BLK];
__device__ int   g_src[MAX_E];
__device__ int   g_e64;          // 1 if edge_index is int64, 0 if int32
__device__ int   g_tick;         // scan1 last-block ticket

// ---------------------------------------------------------------------------
__device__ __forceinline__ unsigned h2_as_u32(__half2 h) {
    union { __half2 h; unsigned u; } cvt; cvt.h = h; return cvt.u;
}
__device__ __forceinline__ __half2 u32_as_h2(unsigned u) {
    union { unsigned u; __half2 h; } cvt; cvt.u = u; return cvt.h;
}
__device__ __forceinline__ int load_idx(const void* edges, long long i, int e64) {
    if (e64) return (int)((const long long*)edges)[i];
    return ((const int*)edges)[i];
}
__device__ __forceinline__ uint32_t smem_u32(const void* p) {
    return (uint32_t)__cvta_generic_to_shared(p);
}

// ---------------------------------------------------------------------------
// L1: zero g_cnt + dtype probe (block 0) + W->fp16 conversion (blocks 1..32)
//     + reset scan ticket.
__global__ void k_init(const void* __restrict__ edges, const float* __restrict__ W,
                       int N, int n) {
    __shared__ int bad;
    const int i = blockIdx.x * blockDim.x + threadIdx.x;
    if (i < n) g_cnt[i] = 0;
    if (blockIdx.x == 0) {
        if (threadIdx.x == 0) { bad = 0; g_tick = 0; }
        __syncthreads();
        if (threadIdx.x < 64) {
            long long v = ((const long long*)edges)[threadIdx.x];
            if (v < 0 || v >= (long long)N) atomicOr(&bad, 1);
        }
        __syncthreads();
        if (threadIdx.x == 0) g_e64 = bad ? 0 : 1;
    } else if (blockIdx.x <= 32) {
        const int j = (blockIdx.x - 1) * 256 + threadIdx.x;  // [0, 8192)
        const float2 w = ((const float2*)W)[j];
        g_Wh2[j] = __floats2half2_rn(w.x, w.y);
    }
}

// L2: histogram over edge targets
__global__ void k_hist(const void* __restrict__ edges, int E, int N) {
    int e = blockIdx.x * blockDim.x + threadIdx.x;
    if (e < E) {
        int c = load_idx(edges, (long long)E + e, g_e64);
        if ((unsigned)c < (unsigned)N) atomicAdd(&g_cnt[c], 1);
    }
}

// L3: per-block scan of g_cnt -> g_rowptr + dinv; last block scans block totals.
__global__ void k_scan1(int n, int nblk) {
    __shared__ int s[SCAN_B];
    __shared__ int isLast;
    const int tid = threadIdx.x;
    const int i   = blockIdx.x * SCAN_B + tid;
    const int v   = (i < n) ? g_cnt[i] : 0;
    if (i < n) g_dinv[i] = rsqrtf((float)(v + 1));   // +1 self loop
    s[tid] = v;
    __syncthreads();
    #pragma unroll
    for (int off = 1; off < SCAN_B; off <<= 1) {
        int t = (tid >= off) ? s[tid - off] : 0;
        __syncthreads();
        s[tid] += t;
        __syncthreads();
    }
    if (i < n) g_rowptr[i] = s[tid] - v;
    if (tid == SCAN_B - 1) g_blk[blockIdx.x] = s[tid];

    // last-block: exclusive scan of block totals
    __threadfence();
    if (tid == 0) isLast = (atomicAdd(&g_tick, 1) == nblk - 1) ? 1 : 0;
    __syncthreads();
    if (isLast) {
        const int bv = (tid < nblk) ? g_blk[tid] : 0;
        s[tid] = (tid < MAX_BLK) ? bv : 0;
        __syncthreads();
        #pragma unroll
        for (int off = 1; off < MAX_BLK; off <<= 1) {
            int t = (tid >= off && tid < MAX_BLK) ? s[tid - off] : 0;
            __syncthreads();
            if (tid < MAX_BLK) s[tid] += t;
            __syncthreads();
        }
        if (tid < nblk) g_blk[tid] = s[tid] - bv;   // exclusive
    }
}

// ---------------------------------------------------------------------------
// Fused LayerNorm -> ReLU -> HMMA GEMM -> *dinv, fp16 out. (stream 1 branch)
// 256 threads, 64 nodes/block. Warp tile 32x32.
__global__ void __launch_bounds__(256) fused_ln_gemm_kernel(
    const float* __restrict__ x,
    const float* __restrict__ gamma,
    const float* __restrict__ beta,
    int N)
{
    extern __shared__ __align__(16) __half smem[];
    __half* A_s = smem;                    // [64][A_STRIDE]
    __half* W_s = smem + 64 * A_STRIDE;    // [128][W_STRIDE]

    const int tid  = threadIdx.x;
    const int warp = tid >> 5;
    const int lane = tid & 31;
    const int node0 = blockIdx.x * 64;

    // ---- Phase 0: stage fp16 W into shared ----
    {
        const uint4* src = (const uint4*)g_Wh2;     // 2048 uint4 (8 halves each)
        #pragma unroll
        for (int i = tid; i < 2048; i += 256) {
            const int row = i >> 4;
            const int c8  = i & 15;
            *(uint4*)&W_s[row * W_STRIDE + c8 * 8] = src[i];
        }
    }

    // ---- Phase A: LayerNorm + ReLU into A_s (fp16, row-major) ----
    #pragma unroll
    for (int rr = 0; rr < 8; rr++) {
        const int n = warp * 8 + rr;
        const int node = node0 + n;
        float v0 = 0.f, v1 = 0.f, v2 = 0.f, v3 = 0.f;
        if (node < N) {
            const float* xr = x + (size_t)node * D;
            v0 = xr[lane]; v1 = xr[lane + 32]; v2 = xr[lane + 64]; v3 = xr[lane + 96];
        }
        float s  = v0 + v1 + v2 + v3;
        float sq = v0 * v0 + v1 * v1 + v2 * v2 + v3 * v3;
        #pragma unroll
        for (int off = 16; off; off >>= 1) {
            s  += __shfl_xor_sync(0xFFFFFFFFu, s,  off);
            sq += __shfl_xor_sync(0xFFFFFFFFu, sq, off);
        }
        const float mu  = s * (1.0f / 128.0f);
        const float var = sq * (1.0f / 128.0f) - mu * mu;
        const float rs  = rsqrtf(var + 1e-5f);
        __half* ar = &A_s[n * A_STRIDE];
        ar[lane]      = __float2half(fmaxf((v0 - mu) * rs * gamma[lane]      + beta[lane],      0.f));
        ar[lane + 32] = __float2half(fmaxf((v1 - mu) * rs * gamma[lane + 32] + beta[lane + 32], 0.f));
        ar[lane + 64] = __float2half(fmaxf((v2 - mu) * rs * gamma[lane + 64] + beta[lane + 64], 0.f));
        ar[lane + 96] = __float2half(fmaxf((v3 - mu) * rs * gamma[lane + 96] + beta[lane + 96], 0.f));
    }
    __syncthreads();

    // ---- Phase B: HMMA. warp tile 32x32: wm = warp>>2, wn = warp&3 ----
    const int wm = warp >> 2;
    const int wn = warp & 3;

    float acc[2][4][4];
    #pragma unroll
    for (int mt = 0; mt < 2; mt++)
        #pragma unroll
        for (int nn = 0; nn < 4; nn++)
            #pragma unroll
            for (int c = 0; c < 4; c++) acc[mt][nn][c] = 0.f;

    const uint32_t a_addr0 = smem_u32(&A_s[(wm * 32 + (lane & 15)) * A_STRIDE + (lane >> 4) * 8]);
    const uint32_t a_addr1 = a_addr0 + 16 * A_STRIDE * 2;
    const uint32_t b_addr0 = smem_u32(&W_s[(lane & 15) * W_STRIDE + wn * 32]);

    #pragma unroll
    for (int kk = 0; kk < 8; kk++) {
        uint32_t b0[4], b1[4];
        const uint32_t b_k = b_addr0 + kk * (16 * W_STRIDE * 2);
        #pragma unroll
        for (int nn = 0; nn < 4; nn++) {
            asm volatile("ldmatrix.sync.aligned.m8n8.x2.trans.shared.b16 {%0,%1}, [%2];"
                         : "=r"(b0[nn]), "=r"(b1[nn])
                         : "r"(b_k + nn * 16));
        }
        uint32_t a[2][4];
        asm volatile("ldmatrix.sync.aligned.m8n8.x4.shared.b16 {%0,%1,%2,%3}, [%4];"
                     : "=r"(a[0][0]), "=r"(a[0][1]), "=r"(a[0][2]), "=r"(a[0][3])
                     : "r"(a_addr0 + kk * 32));
        asm volatile("ldmatrix.sync.aligned.m8n8.x4.shared.b16 {%0,%1,%2,%3}, [%4];"
                     : "=r"(a[1][0]), "=r"(a[1][1]), "=r"(a[1][2]), "=r"(a[1][3])
                     : "r"(a_addr1 + kk * 32));
        #pragma unroll
        for (int mt = 0; mt < 2; mt++)
            #pragma unroll
            for (int nn = 0; nn < 4; nn++)
                asm volatile("mma.sync.aligned.m16n8k16.row.col.f32.f16.f16.f32 "
                             "{%0,%1,%2,%3}, {%4,%5,%6,%7}, {%8,%9}, {%0,%1,%2,%3};"
                             : "+f"(acc[mt][nn][0]), "+f"(acc[mt][nn][1]),
                               "+f"(acc[mt][nn][2]), "+f"(acc[mt][nn][3])
                             : "r"(a[mt][0]), "r"(a[mt][1]), "r"(a[mt][2]), "r"(a[mt][3]),
                               "r"(b0[nn]), "r"(b1[nn]));
    }

    // ---- Epilogue: scale by dinv[node], fp16 store to g_bufh ----
    const int group = lane >> 2;
    const int qp    = lane & 3;
    #pragma unroll
    for (int mt = 0; mt < 2; mt++) {
        const int r0 = node0 + wm * 32 + mt * 16 + group;
        const int r1 = r0 + 8;
        const float dv0 = (r0 < N) ? g_dinv[r0] : 0.f;
        const float dv1 = (r1 < N) ? g_dinv[r1] : 0.f;
        #pragma unroll
        for (int nn = 0; nn < 4; nn++) {
            const int col2 = wn * 16 + nn * 4 + qp;
            if (r0 < N)
                g_bufh[(size_t)r0 * 64 + col2] =
                    __floats2half2_rn(acc[mt][nn][0] * dv0, acc[mt][nn][1] * dv0);
            if (r1 < N)
                g_bufh[(size_t)r1 * 64 + col2] =
                    __floats2half2_rn(acc[mt][nn][2] * dv1, acc[mt][nn][3] * dv1);
        }
    }
}

// ---------------------------------------------------------------------------
// stream-0 branch: add block offsets; init cursors; set rowptr[N]
__global__ void k_scan3(int n, int E) {
    const int i = blockIdx.x * SCAN_B + threadIdx.x;
    if (i < n) {
        int r = g_rowptr[i] + g_blk[blockIdx.x];
        g_rowptr[i] = r;
        g_cur[i]    = r;
    }
    if (blockIdx.x == 0 && threadIdx.x == 0) g_rowptr[n] = E;
}

// CSR fill
__global__ void k_fill(const void* __restrict__ edges, int E, int N) {
    int e = blockIdx.x * blockDim.x + threadIdx.x;
    if (e < E) {
        const int e64 = g_e64;
        int r = load_idx(edges, e, e64);
        int c = load_idx(edges, (long long)E + e, e64);
        if ((unsigned)c < (unsigned)N && (unsigned)r < (unsigned)N) {
            int pos = atomicAdd(&g_cur[c], 1);
            if (pos < MAX_E) g_src[pos] = r;
        }
    }
}

// join: warp-per-node gather: out[i] = dinv[i]*(g[i] + sum_j g[j]) + bias
__global__ void __launch_bounds__(256) k_aggr(float* __restrict__ out,
                                              const float* __restrict__ bias, int N)
{
    const int gt   = blockIdx.x * blockDim.x + threadIdx.x;
    const int node = gt >> 5;
    const int lane = gt & 31;
    if (node >= N) return;

    const int start = g_rowptr[node];
    const int end   = g_rowptr[node + 1];

    float a0, a1, a2, a3;
    {
        const uint2 u = ((const uint2*)(g_bufh + (size_t)node * 64))[lane];
        const float2 f0 = __half22float2(u32_as_h2(u.x));
        const float2 f1 = __half22float2(u32_as_h2(u.y));
        a0 = f0.x; a1 = f0.y; a2 = f1.x; a3 = f1.y;
    }

    int k = start;
    for (; k + 4 <= end; k += 4) {
        const int j0 = g_src[k], j1 = g_src[k + 1], j2 = g_src[k + 2], j3 = g_src[k + 3];
        const uint2 u0 = ((const uint2*)(g_bufh + (size_t)j0 * 64))[lane];
        const uint2 u1 = ((const uint2*)(g_bufh + (size_t)j1 * 64))[lane];
        const uint2 u2 = ((const uint2*)(g_bufh + (size_t)j2 * 64))[lane];
        const uint2 u3 = ((const uint2*)(g_bufh + (size_t)j3 * 64))[lane];
        float2 f;
        f = __half22float2(u32_as_h2(u0.x)); a0 += f.x; a1 += f.y;
        f = __half22float2(u32_as_h2(u0.y)); a2 += f.x; a3 += f.y;
        f = __half22float2(u32_as_h2(u1.x)); a0 += f.x; a1 += f.y;
        f = __half22float2(u32_as_h2(u1.y)); a2 += f.x; a3 += f.y;
        f = __half22float2(u32_as_h2(u2.x)); a0 += f.x; a1 += f.y;
        f = __half22float2(u32_as_h2(u2.y)); a2 += f.x; a3 += f.y;
        f = __half22float2(u32_as_h2(u3.x)); a0 += f.x; a1 += f.y;
        f = __half22float2(u32_as_h2(u3.y)); a2 += f.x; a3 += f.y;
    }
    for (; k < end; k++) {
        const int j = g_src[k];
        const uint2 u = ((const uint2*)(g_bufh + (size_t)j * 64))[lane];
        float2 f;
        f = __half22float2(u32_as_h2(u.x)); a0 += f.x; a1 += f.y;
        f = __half22float2(u32_as_h2(u.y)); a2 += f.x; a3 += f.y;
    }

    const float dvi = g_dinv[node];
    const float4 b = ((const float4*)bias)[lane];
    float4 r;
    r.x = a0 * dvi + b.x;
    r.y = a1 * dvi + b.y;
    r.z = a2 * dvi + b.z;
    r.w = a3 * dvi + b.w;
    ((float4*)(out + (size_t)node * D))[lane] = r;
}

// ---------------------------------------------------------------------------
extern "C" void kernel_launch(void* const* d_in, const int* in_sizes, int n_in,
                              void* d_out, int out_size)
{
    const float* x     = (const float*)d_in[0];
    const void*  edges = (const void*)d_in[1];
    const float* gamma = (const float*)d_in[2];
    const float* beta  = (const float*)d_in[3];
    const float* W     = (const float*)d_in[4];
    const float* bias  = (const float*)d_in[5];
    float*       out   = (float*)d_out;

    const int N = in_sizes[0] / D;
    const int E = in_sizes[1] / 2;
    const int nblk = (N + SCAN_B - 1) / SCAN_B;

    static cudaStream_t s1 = nullptr;
    static cudaEvent_t  evFork = nullptr, evJoin = nullptr;
    if (!s1) {
        cudaFuncSetAttribute(fused_ln_gemm_kernel,
                             cudaFuncAttributeMaxDynamicSharedMemorySize,
                             GEMM_SMEM_BYTES);
        cudaStreamCreateWithFlags(&s1, cudaStreamNonBlocking);
        cudaEventCreateWithFlags(&evFork, cudaEventDisableTiming);
        cudaEventCreateWithFlags(&evJoin, cudaEventDisableTiming);
    }

    // serial prefix on stream 0
    k_init<<<(N + 255) / 256, 256>>>(edges, W, N, N);
    k_hist<<<(E + 255) / 256, 256>>>(edges, E, N);
    k_scan1<<<nblk, SCAN_B>>>(N, nblk);

    // fork: GEMM branch on s1, CSR branch on stream 0
    cudaEventRecord(evFork, 0);
    cudaStreamWaitEvent(s1, evFork, 0);
    fused_ln_gemm_kernel<<<(N + 63) / 64, 256, GEMM_SMEM_BYTES, s1>>>(x, gamma, beta, N);
    cudaEventRecord(evJoin, s1);

    k_scan3<<<nblk, SCAN_B>>>(N, E);
    k_fill<<<(E + 255) / 256, 256>>>(edges, E, N);

    // join
    cudaStreamWaitEvent(0, evJoin, 0);
    k_aggr<<<(N * 32 + 255) / 256, 256>>>(out, bias, N);
}

// round 11
// speedup vs baseline: 1.8543x; 1.0365x over previous
#include <cuda_runtime.h>
#include <cuda_fp16.h>
#include <cstdint>

#define MAX_N   131072
#define MAX_E   1700000
#define D       128
#define SCAN_B  512
#define MAX_BLK 256   // MAX_N / SCAN_B

#define A_STRIDE 136
#define W_STRIDE 136
#define GEMM_SMEM_BYTES ((64 * A_STRIDE + 128 * W_STRIDE) * 2)

// ---- scratch (__device__ globals; no allocations allowed) ----
__device__ __align__(16) __half2 g_bufh[(size_t)MAX_N * 64];  // g = dinv*relu(LN(x))@W, fp16
__device__ __align__(16) __half2 g_Wh2[64 * 128];             // W in fp16, row-major [k][n]
__device__ float g_dinv[MAX_N];
__device__ int   g_cnt[MAX_N];
__device__ int   g_rowptr[MAX_N + 1];
__device__ int   g_cur[MAX_N];
__device__ int   g_blk[MAX_BLK];
__device__ int   g_src[MAX_E];
__device__ int   g_e64;
__device__ int   g_tick;

// ---------------------------------------------------------------------------
__device__ __forceinline__ unsigned h2_as_u32(__half2 h) {
    union { __half2 h; unsigned u; } cvt; cvt.h = h; return cvt.u;
}
__device__ __forceinline__ __half2 u32_as_h2(unsigned u) {
    union { unsigned u; __half2 h; } cvt; cvt.u = u; return cvt.h;
}
__device__ __forceinline__ int load_idx(const void* edges, long long i, int e64) {
    if (e64) return (int)((const long long*)edges)[i];
    return ((const int*)edges)[i];
}
__device__ __forceinline__ uint32_t smem_u32(const void* p) {
    return (uint32_t)__cvta_generic_to_shared(p);
}

// ---------------------------------------------------------------------------
// L1: zero g_cnt + dtype probe (block 0) + W->fp16 (blocks 1..32) + ticket reset.
__global__ void k_init(const void* __restrict__ edges, const float* __restrict__ W,
                       int N, int n) {
    __shared__ int bad;
    const int i = blockIdx.x * blockDim.x + threadIdx.x;
    if (i < n) g_cnt[i] = 0;
    if (blockIdx.x == 0) {
        if (threadIdx.x == 0) { bad = 0; g_tick = 0; }
        __syncthreads();
        if (threadIdx.x < 64) {
            long long v = ((const long long*)edges)[threadIdx.x];
            if (v < 0 || v >= (long long)N) atomicOr(&bad, 1);
        }
        __syncthreads();
        if (threadIdx.x == 0) g_e64 = bad ? 0 : 1;
    } else if (blockIdx.x <= 32) {
        const int j = (blockIdx.x - 1) * 256 + threadIdx.x;  // [0, 8192)
        const float2 w = ((const float2*)W)[j];
        g_Wh2[j] = __floats2half2_rn(w.x, w.y);
    }
}

// L2: histogram over edge targets, 2 edges/thread (vector loads when aligned).
__global__ void k_hist(const void* __restrict__ edges, int E, int N) {
    const int t  = blockIdx.x * blockDim.x + threadIdx.x;
    const int e0 = t * 2;
    if (e0 >= E) return;
    const int e64 = g_e64;
    int c0, c1 = -1;
    const bool two = (e0 + 1 < E);
    if (e64) {
        const long long* p = (const long long*)edges + (long long)E + e0;
        if (two && ((E & 1) == 0)) {
            const longlong2 v = *(const longlong2*)p;
            c0 = (int)v.x; c1 = (int)v.y;
        } else {
            c0 = (int)p[0];
            if (two) c1 = (int)p[1];
        }
    } else {
        const int* p = (const int*)edges + (long long)E + e0;
        if (two && ((E & 1) == 0)) {
            const int2 v = *(const int2*)p;
            c0 = v.x; c1 = v.y;
        } else {
            c0 = p[0];
            if (two) c1 = p[1];
        }
    }
    if ((unsigned)c0 < (unsigned)N) atomicAdd(&g_cnt[c0], 1);
    if (two && (unsigned)c1 < (unsigned)N) atomicAdd(&g_cnt[c1], 1);
}

// L3: per-block scan + dinv; last block scans block totals.
__global__ void k_scan1(int n, int nblk) {
    __shared__ int s[SCAN_B];
    __shared__ int isLast;
    const int tid = threadIdx.x;
    const int i   = blockIdx.x * SCAN_B + tid;
    const int v   = (i < n) ? g_cnt[i] : 0;
    if (i < n) g_dinv[i] = rsqrtf((float)(v + 1));
    s[tid] = v;
    __syncthreads();
    #pragma unroll
    for (int off = 1; off < SCAN_B; off <<= 1) {
        int t = (tid >= off) ? s[tid - off] : 0;
        __syncthreads();
        s[tid] += t;
        __syncthreads();
    }
    if (i < n) g_rowptr[i] = s[tid] - v;
    if (tid == SCAN_B - 1) g_blk[blockIdx.x] = s[tid];

    __threadfence();
    if (tid == 0) isLast = (atomicAdd(&g_tick, 1) == nblk - 1) ? 1 : 0;
    __syncthreads();
    if (isLast) {
        const int bv = (tid < nblk) ? g_blk[tid] : 0;
        s[tid] = (tid < MAX_BLK) ? bv : 0;
        __syncthreads();
        #pragma unroll
        for (int off = 1; off < MAX_BLK; off <<= 1) {
            int t = (tid >= off && tid < MAX_BLK) ? s[tid - off] : 0;
            __syncthreads();
            if (tid < MAX_BLK) s[tid] += t;
            __syncthreads();
        }
        if (tid < nblk) g_blk[tid] = s[tid] - bv;
    }
}

// ---------------------------------------------------------------------------
// Fused LayerNorm -> ReLU -> HMMA GEMM -> *dinv, fp16 out. (stream-1 branch)
__global__ void __launch_bounds__(256) fused_ln_gemm_kernel(
    const float* __restrict__ x,
    const float* __restrict__ gamma,
    const float* __restrict__ beta,
    int N)
{
    extern __shared__ __align__(16) __half smem[];
    __half* A_s = smem;                    // [64][A_STRIDE]
    __half* W_s = smem + 64 * A_STRIDE;    // [128][W_STRIDE]

    const int tid  = threadIdx.x;
    const int warp = tid >> 5;
    const int lane = tid & 31;
    const int node0 = blockIdx.x * 64;

    {
        const uint4* src = (const uint4*)g_Wh2;
        #pragma unroll
        for (int i = tid; i < 2048; i += 256) {
            const int row = i >> 4;
            const int c8  = i & 15;
            *(uint4*)&W_s[row * W_STRIDE + c8 * 8] = src[i];
        }
    }

    #pragma unroll
    for (int rr = 0; rr < 8; rr++) {
        const int n = warp * 8 + rr;
        const int node = node0 + n;
        float v0 = 0.f, v1 = 0.f, v2 = 0.f, v3 = 0.f;
        if (node < N) {
            const float* xr = x + (size_t)node * D;
            v0 = xr[lane]; v1 = xr[lane + 32]; v2 = xr[lane + 64]; v3 = xr[lane + 96];
        }
        float s  = v0 + v1 + v2 + v3;
        float sq = v0 * v0 + v1 * v1 + v2 * v2 + v3 * v3;
        #pragma unroll
        for (int off = 16; off; off >>= 1) {
            s  += __shfl_xor_sync(0xFFFFFFFFu, s,  off);
            sq += __shfl_xor_sync(0xFFFFFFFFu, sq, off);
        }
        const float mu  = s * (1.0f / 128.0f);
        const float var = sq * (1.0f / 128.0f) - mu * mu;
        const float rs  = rsqrtf(var + 1e-5f);
        __half* ar = &A_s[n * A_STRIDE];
        ar[lane]      = __float2half(fmaxf((v0 - mu) * rs * gamma[lane]      + beta[lane],      0.f));
        ar[lane + 32] = __float2half(fmaxf((v1 - mu) * rs * gamma[lane + 32] + beta[lane + 32], 0.f));
        ar[lane + 64] = __float2half(fmaxf((v2 - mu) * rs * gamma[lane + 64] + beta[lane + 64], 0.f));
        ar[lane + 96] = __float2half(fmaxf((v3 - mu) * rs * gamma[lane + 96] + beta[lane + 96], 0.f));
    }
    __syncthreads();

    const int wm = warp >> 2;
    const int wn = warp & 3;

    float acc[2][4][4];
    #pragma unroll
    for (int mt = 0; mt < 2; mt++)
        #pragma unroll
        for (int nn = 0; nn < 4; nn++)
            #pragma unroll
            for (int c = 0; c < 4; c++) acc[mt][nn][c] = 0.f;

    const uint32_t a_addr0 = smem_u32(&A_s[(wm * 32 + (lane & 15)) * A_STRIDE + (lane >> 4) * 8]);
    const uint32_t a_addr1 = a_addr0 + 16 * A_STRIDE * 2;
    const uint32_t b_addr0 = smem_u32(&W_s[(lane & 15) * W_STRIDE + wn * 32]);

    #pragma unroll
    for (int kk = 0; kk < 8; kk++) {
        uint32_t b0[4], b1[4];
        const uint32_t b_k = b_addr0 + kk * (16 * W_STRIDE * 2);
        #pragma unroll
        for (int nn = 0; nn < 4; nn++) {
            asm volatile("ldmatrix.sync.aligned.m8n8.x2.trans.shared.b16 {%0,%1}, [%2];"
                         : "=r"(b0[nn]), "=r"(b1[nn])
                         : "r"(b_k + nn * 16));
        }
        uint32_t a[2][4];
        asm volatile("ldmatrix.sync.aligned.m8n8.x4.shared.b16 {%0,%1,%2,%3}, [%4];"
                     : "=r"(a[0][0]), "=r"(a[0][1]), "=r"(a[0][2]), "=r"(a[0][3])
                     : "r"(a_addr0 + kk * 32));
        asm volatile("ldmatrix.sync.aligned.m8n8.x4.shared.b16 {%0,%1,%2,%3}, [%4];"
                     : "=r"(a[1][0]), "=r"(a[1][1]), "=r"(a[1][2]), "=r"(a[1][3])
                     : "r"(a_addr1 + kk * 32));
        #pragma unroll
        for (int mt = 0; mt < 2; mt++)
            #pragma unroll
            for (int nn = 0; nn < 4; nn++)
                asm volatile("mma.sync.aligned.m16n8k16.row.col.f32.f16.f16.f32 "
                             "{%0,%1,%2,%3}, {%4,%5,%6,%7}, {%8,%9}, {%0,%1,%2,%3};"
                             : "+f"(acc[mt][nn][0]), "+f"(acc[mt][nn][1]),
                               "+f"(acc[mt][nn][2]), "+f"(acc[mt][nn][3])
                             : "r"(a[mt][0]), "r"(a[mt][1]), "r"(a[mt][2]), "r"(a[mt][3]),
                               "r"(b0[nn]), "r"(b1[nn]));
    }

    const int group = lane >> 2;
    const int qp    = lane & 3;
    #pragma unroll
    for (int mt = 0; mt < 2; mt++) {
        const int r0 = node0 + wm * 32 + mt * 16 + group;
        const int r1 = r0 + 8;
        const float dv0 = (r0 < N) ? g_dinv[r0] : 0.f;
        const float dv1 = (r1 < N) ? g_dinv[r1] : 0.f;
        #pragma unroll
        for (int nn = 0; nn < 4; nn++) {
            const int col2 = wn * 16 + nn * 4 + qp;
            if (r0 < N)
                g_bufh[(size_t)r0 * 64 + col2] =
                    __floats2half2_rn(acc[mt][nn][0] * dv0, acc[mt][nn][1] * dv0);
            if (r1 < N)
                g_bufh[(size_t)r1 * 64 + col2] =
                    __floats2half2_rn(acc[mt][nn][2] * dv1, acc[mt][nn][3] * dv1);
        }
    }
}

// ---------------------------------------------------------------------------
// stream-0 branch: add block offsets; init cursors; set rowptr[N]
__global__ void k_scan3(int n, int E) {
    const int i = blockIdx.x * SCAN_B + threadIdx.x;
    if (i < n) {
        int r = g_rowptr[i] + g_blk[blockIdx.x];
        g_rowptr[i] = r;
        g_cur[i]    = r;
    }
    if (blockIdx.x == 0 && threadIdx.x == 0) g_rowptr[n] = E;
}

// CSR fill, 2 edges/thread.
__global__ void k_fill(const void* __restrict__ edges, int E, int N) {
    const int t  = blockIdx.x * blockDim.x + threadIdx.x;
    const int e0 = t * 2;
    if (e0 >= E) return;
    const int e64 = g_e64;
    const bool two = (e0 + 1 < E);
    int r0, c0, r1 = -1, c1 = -1;
    if (e64) {
        const long long* pr = (const long long*)edges + e0;
        const long long* pc = (const long long*)edges + (long long)E + e0;
        if (two) {
            const longlong2 vr = *(const longlong2*)pr;     // e0 even -> 16B aligned
            r0 = (int)vr.x; r1 = (int)vr.y;
            if ((E & 1) == 0) {
                const longlong2 vc = *(const longlong2*)pc;
                c0 = (int)vc.x; c1 = (int)vc.y;
            } else { c0 = (int)pc[0]; c1 = (int)pc[1]; }
        } else { r0 = (int)pr[0]; c0 = (int)pc[0]; }
    } else {
        const int* pr = (const int*)edges + e0;
        const int* pc = (const int*)edges + (long long)E + e0;
        if (two) {
            const int2 vr = *(const int2*)pr;
            r0 = vr.x; r1 = vr.y;
            if ((E & 1) == 0) {
                const int2 vc = *(const int2*)pc;
                c0 = vc.x; c1 = vc.y;
            } else { c0 = pc[0]; c1 = pc[1]; }
        } else { r0 = pr[0]; c0 = pc[0]; }
    }
    if ((unsigned)c0 < (unsigned)N && (unsigned)r0 < (unsigned)N) {
        int pos = atomicAdd(&g_cur[c0], 1);
        if (pos < MAX_E) g_src[pos] = r0;
    }
    if (two && (unsigned)c1 < (unsigned)N && (unsigned)r1 < (unsigned)N) {
        int pos = atomicAdd(&g_cur[c1], 1);
        if (pos < MAX_E) g_src[pos] = r1;
    }
}

// join: warp-per-node gather with fp16 tree reduction over 4-neighbor groups.
__global__ void __launch_bounds__(256) k_aggr(float* __restrict__ out,
                                              const float* __restrict__ bias, int N)
{
    const int gt   = blockIdx.x * blockDim.x + threadIdx.x;
    const int node = gt >> 5;
    const int lane = gt & 31;
    if (node >= N) return;

    const int start = g_rowptr[node];
    const int end   = g_rowptr[node + 1];

    float a0, a1, a2, a3;
    {
        const uint2 u = ((const uint2*)(g_bufh + (size_t)node * 64))[lane];
        const float2 f0 = __half22float2(u32_as_h2(u.x));
        const float2 f1 = __half22float2(u32_as_h2(u.y));
        a0 = f0.x; a1 = f0.y; a2 = f1.x; a3 = f1.y;
    }

    int k = start;
    for (; k + 4 <= end; k += 4) {
        const int j0 = g_src[k], j1 = g_src[k + 1], j2 = g_src[k + 2], j3 = g_src[k + 3];
        const uint2 u0 = ((const uint2*)(g_bufh + (size_t)j0 * 64))[lane];
        const uint2 u1 = ((const uint2*)(g_bufh + (size_t)j1 * 64))[lane];
        const uint2 u2 = ((const uint2*)(g_bufh + (size_t)j2 * 64))[lane];
        const uint2 u3 = ((const uint2*)(g_bufh + (size_t)j3 * 64))[lane];
        // fp16 tree sum of 4 neighbors (values |g| <~ 3, sums <~ 12: safe in fp16)
        const __half2 sx = __hadd2(__hadd2(u32_as_h2(u0.x), u32_as_h2(u1.x)),
                                   __hadd2(u32_as_h2(u2.x), u32_as_h2(u3.x)));
        const __half2 sy = __hadd2(__hadd2(u32_as_h2(u0.y), u32_as_h2(u1.y)),
                                   __hadd2(u32_as_h2(u2.y), u32_as_h2(u3.y)));
        const float2 f0 = __half22float2(sx);
        const float2 f1 = __half22float2(sy);
        a0 += f0.x; a1 += f0.y; a2 += f1.x; a3 += f1.y;
    }
    for (; k < end; k++) {
        const int j = g_src[k];
        const uint2 u = ((const uint2*)(g_bufh + (size_t)j * 64))[lane];
        float2 f;
        f = __half22float2(u32_as_h2(u.x)); a0 += f.x; a1 += f.y;
        f = __half22float2(u32_as_h2(u.y)); a2 += f.x; a3 += f.y;
    }

    const float dvi = g_dinv[node];
    const float4 b = ((const float4*)bias)[lane];
    float4 r;
    r.x = a0 * dvi + b.x;
    r.y = a1 * dvi + b.y;
    r.z = a2 * dvi + b.z;
    r.w = a3 * dvi + b.w;
    ((float4*)(out + (size_t)node * D))[lane] = r;
}

// ---------------------------------------------------------------------------
extern "C" void kernel_launch(void* const* d_in, const int* in_sizes, int n_in,
                              void* d_out, int out_size)
{
    const float* x     = (const float*)d_in[0];
    const void*  edges = (const void*)d_in[1];
    const float* gamma = (const float*)d_in[2];
    const float* beta  = (const float*)d_in[3];
    const float* W     = (const float*)d_in[4];
    const float* bias  = (const float*)d_in[5];
    float*       out   = (float*)d_out;

    const int N = in_sizes[0] / D;
    const int E = in_sizes[1] / 2;
    const int nblk = (N + SCAN_B - 1) / SCAN_B;
    const int halfE = (E + 1) / 2;

    static cudaStream_t s1 = nullptr;
    static cudaEvent_t  evFork = nullptr, evJoin = nullptr;
    if (!s1) {
        cudaFuncSetAttribute(fused_ln_gemm_kernel,
                             cudaFuncAttributeMaxDynamicSharedMemorySize,
                             GEMM_SMEM_BYTES);
        cudaStreamCreateWithFlags(&s1, cudaStreamNonBlocking);
        cudaEventCreateWithFlags(&evFork, cudaEventDisableTiming);
        cudaEventCreateWithFlags(&evJoin, cudaEventDisableTiming);
    }

    // serial prefix on stream 0
    k_init<<<(N + 255) / 256, 256>>>(edges, W, N, N);
    k_hist<<<(halfE + 255) / 256, 256>>>(edges, E, N);
    k_scan1<<<nblk, SCAN_B>>>(N, nblk);

    // fork: GEMM on s1, CSR branch on stream 0
    cudaEventRecord(evFork, 0);
    cudaStreamWaitEvent(s1, evFork, 0);
    fused_ln_gemm_kernel<<<(N + 63) / 64, 256, GEMM_SMEM_BYTES, s1>>>(x, gamma, beta, N);
    cudaEventRecord(evJoin, s1);

    k_scan3<<<nblk, SCAN_B>>>(N, E);
    k_fill<<<(halfE + 255) / 256, 256>>>(edges, E, N);

    // join
    cudaStreamWaitEvent(0, evJoin, 0);
    k_aggr<<<(N * 32 + 255) / 256, 256>>>(out, bias, N);
}